// round 1
// baseline (speedup 1.0000x reference)
#include <cuda_runtime.h>
#include <math.h>

#define T_    2048
#define D_    2048
#define HQ_   32
#define HKV_  4
#define HD_   128
#define E_    64
#define TOPK_ 8
#define F_    768
#define NTOK  (T_ * TOPK_)

// ---------------- scratch (static device globals; no allocation) ----------------
__device__ float g_hnorm[T_ * D_];
__device__ float g_q[T_ * HQ_ * HD_];
__device__ float g_k[T_ * HKV_ * HD_];
__device__ float g_v[T_ * HKV_ * HD_];
__device__ float g_attn[T_ * HQ_ * HD_];
__device__ float g_attnproj[T_ * D_];
__device__ float g_res[T_ * D_];
__device__ float g_h2[T_ * D_];
__device__ float g_logits[T_ * E_];
__device__ float g_topv[NTOK];
__device__ int   g_topi[NTOK];
__device__ int   g_cnt[E_];
__device__ int   g_cur[E_];
__device__ int   g_off[E_ + 1];
__device__ int   g_ptok[NTOK];
__device__ int   g_rowof[NTOK];
__device__ float g_gate[NTOK * F_];
__device__ float g_up[NTOK * F_];
__device__ float g_ye[(size_t)NTOK * D_];
__device__ int   g_segT[2] = {0, T_};

__device__ __forceinline__ float* buf_ptr(int id) {
    switch (id) {
        case 0: return g_hnorm;
        case 1: return g_q;
        case 2: return g_k;
        case 3: return g_v;
        case 4: return g_attn;
        case 5: return g_attnproj;
        case 6: return g_h2;
        case 7: return g_logits;
        case 8: return g_gate;
        case 9: return g_up;
        default: return g_ye;
    }
}

// ---------------- rmsnorm over D=2048 ----------------
__global__ void rmsnorm_kernel(const float* __restrict__ xext, int oid,
                               const float* __restrict__ scale) {
    const float* x = xext ? xext : g_res;
    float* out = buf_ptr(oid);
    int t = blockIdx.x;
    int tid = threadIdx.x;
    const float* xr = x + (size_t)t * D_;
    float v[8];
    float ss = 0.f;
#pragma unroll
    for (int j = 0; j < 8; j++) { v[j] = xr[tid + j * 256]; ss += v[j] * v[j]; }
#pragma unroll
    for (int o = 16; o; o >>= 1) ss += __shfl_xor_sync(0xffffffffu, ss, o);
    __shared__ float ws[8];
    if ((tid & 31) == 0) ws[tid >> 5] = ss;
    __syncthreads();
    float tot = 0.f;
#pragma unroll
    for (int w = 0; w < 8; w++) tot += ws[w];
    float inv = rsqrtf(tot / (float)D_ + 1e-6f);
    float* orow = out + (size_t)t * D_;
#pragma unroll
    for (int j = 0; j < 8; j++)
        orow[tid + j * 256] = v[j] * inv * scale[tid + j * 256];
}

// ---------------- generic (optionally expert-grouped, gathered) SGEMM ----------------
// C[row, 0:N) = X[arow, 0:K) @ W_e[K, N], row in [seg[e], seg[e+1])
// arow = usemap ? g_ptok[row] : row
__global__ void __launch_bounds__(256) gemm_kernel(
    int xid, const float* __restrict__ W, int cid,
    int segid, int usemap, int K, int N, long wstride) {
    const int* seg = segid ? g_off : g_segT;
    int e = blockIdx.z;
    int segs = seg[e], sege = seg[e + 1];
    int m0 = segs + blockIdx.y * 128;
    if (m0 >= sege) return;
    const float* X = buf_ptr(xid);
    float* C = buf_ptr(cid);
    const float* Wp = W + (long)e * wstride;
    int n0 = blockIdx.x * 128;

    __shared__ float As[8][132];
    __shared__ float Bs[8][128];

    int tid = threadIdx.x;
    int am = tid >> 1, ak = (tid & 1) * 4;
    int bk = tid >> 5, bn = (tid & 31) * 4;
    int tx = tid & 15, ty = tid >> 4;

    int gr = m0 + am;
    bool avalid = gr < sege;
    int arow = avalid ? (usemap ? g_ptok[gr] : gr) : 0;
    const float* ap = X + (long)arow * K + ak;
    const float* bp = Wp + (long)bk * N + n0 + bn;
    bool bvalid = (n0 + bn) < N;

    float acc[8][8];
#pragma unroll
    for (int i = 0; i < 8; i++)
#pragma unroll
        for (int j = 0; j < 8; j++) acc[i][j] = 0.f;

    for (int k0 = 0; k0 < K; k0 += 8) {
        float4 a4 = avalid ? *(const float4*)(ap + k0) : make_float4(0, 0, 0, 0);
        float4 b4 = bvalid ? *(const float4*)(bp + (long)k0 * N) : make_float4(0, 0, 0, 0);
        __syncthreads();
        As[ak + 0][am] = a4.x;
        As[ak + 1][am] = a4.y;
        As[ak + 2][am] = a4.z;
        As[ak + 3][am] = a4.w;
        *(float4*)&Bs[bk][bn] = b4;
        __syncthreads();
#pragma unroll
        for (int kk = 0; kk < 8; kk++) {
            float ar[8], br[8];
            *(float4*)&ar[0] = *(const float4*)&As[kk][ty * 8];
            *(float4*)&ar[4] = *(const float4*)&As[kk][ty * 8 + 4];
            *(float4*)&br[0] = *(const float4*)&Bs[kk][tx * 8];
            *(float4*)&br[4] = *(const float4*)&Bs[kk][tx * 8 + 4];
#pragma unroll
            for (int i = 0; i < 8; i++)
#pragma unroll
                for (int j = 0; j < 8; j++) acc[i][j] += ar[i] * br[j];
        }
    }
    bool cn = (n0 + tx * 8) < N;
#pragma unroll
    for (int i = 0; i < 8; i++) {
        int row = m0 + ty * 8 + i;
        if (row < sege && cn) {
            float* cp = C + (long)row * N + n0 + tx * 8;
            *(float4*)cp = make_float4(acc[i][0], acc[i][1], acc[i][2], acc[i][3]);
            *(float4*)(cp + 4) = make_float4(acc[i][4], acc[i][5], acc[i][6], acc[i][7]);
        }
    }
}

// ---------------- per-head rmsnorm (HD=128) + RoPE, in place ----------------
__global__ void qknorm_rope_kernel(int bid, const int* __restrict__ positions,
                                   const float* __restrict__ sc, int H) {
    float* buf = buf_ptr(bid);
    int t = blockIdx.x, h = blockIdx.y;
    float* x = buf + ((size_t)t * H + h) * HD_;
    int d = threadIdx.x;
    float v = x[d];
    float sq = v * v;
#pragma unroll
    for (int o = 16; o; o >>= 1) sq += __shfl_xor_sync(0xffffffffu, sq, o);
    __shared__ float ws[4];
    __shared__ float sh[HD_];
    if ((d & 31) == 0) ws[d >> 5] = sq;
    __syncthreads();
    float tot = ws[0] + ws[1] + ws[2] + ws[3];
    float xn = v * rsqrtf(tot / 128.f + 1e-6f) * sc[d];
    sh[d] = xn;
    __syncthreads();
    if (d < 64) {
        double invf = exp(-13.815510557964274 * ((double)d / 64.0));
        double ang = (double)positions[t] * invf;
        float c = (float)cos(ang);
        float s = (float)sin(ang);
        float x1 = sh[d], x2 = sh[d + 64];
        x[d] = x1 * c - x2 * s;
        x[d + 64] = x2 * c + x1 * s;
    }
}

// ---------------- causal flash attention ----------------
// grid: (T/32, HQ); block 128. 4 threads per q-row, each owns a 32-wide d-quarter.
__global__ void __launch_bounds__(128) attn_kernel() {
    int hq = blockIdx.y;
    int kv = hq >> 3;
    int q0 = blockIdx.x * 32;
    int tid = threadIdx.x;
    int r = tid >> 2, dq = tid & 3;
    const float* qp = g_q + ((size_t)(q0 + r) * HQ_ + hq) * HD_ + dq * 32;
    float q[32], o[32];
#pragma unroll
    for (int i = 0; i < 32; i++) { q[i] = qp[i]; o[i] = 0.f; }
    float m = -INFINITY, l = 0.f;
    __shared__ float Ks[32][HD_];
    __shared__ float Vs[32][HD_];
    const float scale = 0.08838834764831845f;  // 128^-0.5

    for (int c0 = 0; c0 <= q0 + 31; c0 += 32) {
        __syncthreads();
        for (int idx = tid; idx < 32 * HD_; idx += 128) {
            int row = idx >> 7, col = idx & 127;
            Ks[row][col] = g_k[((size_t)(c0 + row) * HKV_ + kv) * HD_ + col];
            Vs[row][col] = g_v[((size_t)(c0 + row) * HKV_ + kv) * HD_ + col];
        }
        __syncthreads();
        float s[32];
        float tmax = -INFINITY;
#pragma unroll
        for (int c = 0; c < 32; c++) {
            float p = 0.f;
#pragma unroll
            for (int i = 0; i < 32; i++) p += q[i] * Ks[c][dq * 32 + i];
            p += __shfl_xor_sync(0xffffffffu, p, 1);
            p += __shfl_xor_sync(0xffffffffu, p, 2);
            p *= scale;
            if (c0 + c > q0 + r) p = -INFINITY;
            s[c] = p;
            tmax = fmaxf(tmax, p);
        }
        float mnew = fmaxf(m, tmax);
        float corr = __expf(m - mnew);
        l *= corr;
#pragma unroll
        for (int i = 0; i < 32; i++) o[i] *= corr;
#pragma unroll
        for (int c = 0; c < 32; c++) {
            float p = __expf(s[c] - mnew);
            l += p;
#pragma unroll
            for (int i = 0; i < 32; i++) o[i] += p * Vs[c][dq * 32 + i];
        }
        m = mnew;
    }
    float invl = 1.f / l;
    float* op = g_attn + ((size_t)(q0 + r) * HQ_ + hq) * HD_ + dq * 32;
#pragma unroll
    for (int i = 0; i < 32; i++) op[i] = o[i] * invl;
}

// ---------------- residual add: res = attnproj + hidden; also emit residual output ----------------
__global__ void resadd_kernel(const float* __restrict__ hidden, float* __restrict__ outres) {
    for (int i = blockIdx.x * 256 + threadIdx.x; i < T_ * D_; i += gridDim.x * 256) {
        float r = g_attnproj[i] + hidden[i];
        g_res[i] = r;
        outres[i] = r;
    }
}

// ---------------- router top-k (one warp per token) ----------------
__global__ void topk_kernel() {
    int t = blockIdx.x * 8 + (threadIdx.x >> 5);
    int lane = threadIdx.x & 31;
    const float* lg = g_logits + (size_t)t * E_;
    float v0 = lg[lane], v1 = lg[lane + 32];
    float mx = fmaxf(v0, v1);
#pragma unroll
    for (int o = 16; o; o >>= 1) mx = fmaxf(mx, __shfl_xor_sync(0xffffffffu, mx, o));
    float e0 = expf(v0 - mx), e1 = expf(v1 - mx);
    float ssum = e0 + e1;
#pragma unroll
    for (int o = 16; o; o >>= 1) ssum += __shfl_xor_sync(0xffffffffu, ssum, o);
    float p0 = e0 / ssum, p1 = e1 / ssum;
    float selv[TOPK_];
    int seli[TOPK_];
#pragma unroll
    for (int it = 0; it < TOPK_; it++) {
        float bv; int bi;
        if (p0 >= p1) { bv = p0; bi = lane; } else { bv = p1; bi = lane + 32; }
#pragma unroll
        for (int o = 16; o; o >>= 1) {
            float ov = __shfl_xor_sync(0xffffffffu, bv, o);
            int oi = __shfl_xor_sync(0xffffffffu, bi, o);
            if (ov > bv || (ov == bv && oi < bi)) { bv = ov; bi = oi; }
        }
        selv[it] = bv;
        seli[it] = bi;
        if (bi == lane) p0 = -1.f;
        if (bi == lane + 32) p1 = -1.f;
    }
    float tot = 0.f;
#pragma unroll
    for (int it = 0; it < TOPK_; it++) tot += selv[it];
    if (lane == 0) {
#pragma unroll
        for (int it = 0; it < TOPK_; it++) {
            g_topv[t * TOPK_ + it] = selv[it] / tot;
            g_topi[t * TOPK_ + it] = seli[it];
        }
    }
}

// ---------------- MoE routing bookkeeping ----------------
__global__ void zero_kernel() {
    int i = threadIdx.x;
    if (i < E_) { g_cnt[i] = 0; g_cur[i] = 0; }
}
__global__ void count_kernel() {
    int i = blockIdx.x * 256 + threadIdx.x;
    if (i < NTOK) atomicAdd(&g_cnt[g_topi[i]], 1);
}
__global__ void scan_kernel() {
    if (threadIdx.x == 0) {
        int a = 0;
        for (int e = 0; e < E_; e++) { g_off[e] = a; a += g_cnt[e]; }
        g_off[E_] = a;
    }
}
__global__ void assign_kernel() {
    int i = blockIdx.x * 256 + threadIdx.x;
    if (i < NTOK) {
        int e = g_topi[i];
        int r = g_off[e] + atomicAdd(&g_cur[e], 1);
        g_ptok[r] = i >> 3;   // token id
        g_rowof[i] = r;
    }
}

// ---------------- silu(gate) * up, in place into g_gate ----------------
__global__ void silu_mul_kernel() {
    for (int i = blockIdx.x * 256 + threadIdx.x; i < NTOK * F_; i += gridDim.x * 256) {
        float g = g_gate[i];
        float u = g_up[i];
        g_gate[i] = g / (1.f + __expf(-g)) * u;
    }
}

// ---------------- combine expert outputs per token ----------------
__global__ void combine_kernel(float* __restrict__ out) {
    int t = blockIdx.x;
    float w[TOPK_];
    int rw[TOPK_];
#pragma unroll
    for (int j = 0; j < TOPK_; j++) {
        w[j] = g_topv[t * TOPK_ + j];
        rw[j] = g_rowof[t * TOPK_ + j];
    }
    for (int d = threadIdx.x; d < D_; d += 256) {
        float acc = 0.f;
#pragma unroll
        for (int j = 0; j < TOPK_; j++)
            acc += w[j] * g_ye[(size_t)rw[j] * D_ + d];
        out[(size_t)t * D_ + d] = acc;
    }
}

// ---------------- launch ----------------
extern "C" void kernel_launch(void* const* d_in, const int* in_sizes, int n_in,
                              void* d_out, int out_size) {
    const int* positions = (const int*)d_in[0];
    const float* hidden = (const float*)d_in[1];
    const float* in_ln = (const float*)d_in[2];
    const float* post_ln = (const float*)d_in[3];
    const float* qns = (const float*)d_in[4];
    const float* kns = (const float*)d_in[5];
    const float* wq = (const float*)d_in[6];
    const float* wk = (const float*)d_in[7];
    const float* wv = (const float*)d_in[8];
    const float* wo = (const float*)d_in[9];
    const float* wr = (const float*)d_in[10];
    const float* wg = (const float*)d_in[11];
    const float* wu = (const float*)d_in[12];
    const float* wd = (const float*)d_in[13];
    float* out = (float*)d_out;

    // pre-attention norm + QKV projections
    rmsnorm_kernel<<<T_, 256>>>(hidden, 0, in_ln);
    gemm_kernel<<<dim3(32, 16, 1), 256>>>(0, wq, 1, 0, 0, D_, HQ_ * HD_, 0);
    gemm_kernel<<<dim3(4, 16, 1), 256>>>(0, wk, 2, 0, 0, D_, HKV_ * HD_, 0);
    gemm_kernel<<<dim3(4, 16, 1), 256>>>(0, wv, 3, 0, 0, D_, HKV_ * HD_, 0);
    // per-head rmsnorm + rope
    qknorm_rope_kernel<<<dim3(T_, HQ_), HD_>>>(1, positions, qns, HQ_);
    qknorm_rope_kernel<<<dim3(T_, HKV_), HD_>>>(2, positions, kns, HKV_);
    // causal attention + output projection + residual
    attn_kernel<<<dim3(T_ / 32, HQ_), 128>>>();
    gemm_kernel<<<dim3(16, 16, 1), 256>>>(4, wo, 5, 0, 0, HQ_ * HD_, D_, 0);
    resadd_kernel<<<2048, 256>>>(hidden, out + (size_t)T_ * D_);
    // post-attention norm + router + top-k
    rmsnorm_kernel<<<T_, 256>>>(nullptr, 6, post_ln);
    gemm_kernel<<<dim3(1, 16, 1), 256>>>(6, wr, 7, 0, 0, D_, E_, 0);
    topk_kernel<<<T_ / 8, 256>>>();
    // expert grouping
    zero_kernel<<<1, 64>>>();
    count_kernel<<<NTOK / 256, 256>>>();
    scan_kernel<<<1, 32>>>();
    assign_kernel<<<NTOK / 256, 256>>>();
    // expert GEMMs (grouped, gathered)
    gemm_kernel<<<dim3(6, 16, 64), 256>>>(6, wg, 8, 1, 1, D_, F_, (long)D_ * F_);
    gemm_kernel<<<dim3(6, 16, 64), 256>>>(6, wu, 9, 1, 1, D_, F_, (long)D_ * F_);
    silu_mul_kernel<<<4096, 256>>>();
    gemm_kernel<<<dim3(16, 16, 64), 256>>>(8, wd, 10, 1, 0, F_, D_, (long)F_ * D_);
    combine_kernel<<<T_, 256>>>(out);
}

// round 3
// speedup vs baseline: 1.4270x; 1.4270x over previous
#include <cuda_runtime.h>
#include <cuda_bf16.h>
#include <math.h>
#include <stdint.h>

#define T_    2048
#define D_    2048
#define HQ_   32
#define HKV_  4
#define HD_   128
#define E_    64
#define TOPK_ 8
#define F_    768
#define NTOK  (T_ * TOPK_)

// ---------------- scratch (static device globals; no allocation) ----------------
__device__ float g_hnorm[T_ * D_];
__device__ float g_q[T_ * HQ_ * HD_];
__device__ float g_k[T_ * HKV_ * HD_];
__device__ float g_v[T_ * HKV_ * HD_];
__device__ float g_attn[T_ * HQ_ * HD_];
__device__ float g_attnproj[T_ * D_];
__device__ float g_res[T_ * D_];
__device__ float g_h2[T_ * D_];
__device__ float g_logits[T_ * E_];
__device__ float g_topv[NTOK];
__device__ int   g_topi[NTOK];
__device__ int   g_cnt[E_];
__device__ int   g_cur[E_];
__device__ int   g_off[E_ + 1];
__device__ int   g_ptok[NTOK];
__device__ int   g_rowof[NTOK];
__device__ float g_gate[NTOK * F_];
__device__ float g_up[NTOK * F_];
__device__ float g_ye[(size_t)NTOK * D_];
__device__ int   g_segT[2] = {0, T_};

// activation hi/lo bf16 buffers
__device__ __align__(16) __nv_bfloat16 g_a0h[T_ * D_];            // hnorm
__device__ __align__(16) __nv_bfloat16 g_a0l[T_ * D_];
__device__ __align__(16) __nv_bfloat16 g_a1h[T_ * HQ_ * HD_];     // attn out
__device__ __align__(16) __nv_bfloat16 g_a1l[T_ * HQ_ * HD_];
__device__ __align__(16) __nv_bfloat16 g_a2h[T_ * D_];            // h2
__device__ __align__(16) __nv_bfloat16 g_a2l[T_ * D_];
__device__ __align__(16) __nv_bfloat16 g_a3h[(size_t)NTOK * F_];  // silu*up
__device__ __align__(16) __nv_bfloat16 g_a3l[(size_t)NTOK * F_];

// transposed bf16 hi/lo weight copies ([N,K] K-major per expert)
__device__ __align__(16) __nv_bfloat16 g_wq_h[(size_t)4096 * 2048];
__device__ __align__(16) __nv_bfloat16 g_wq_l[(size_t)4096 * 2048];
__device__ __align__(16) __nv_bfloat16 g_wk_h[(size_t)512 * 2048];
__device__ __align__(16) __nv_bfloat16 g_wk_l[(size_t)512 * 2048];
__device__ __align__(16) __nv_bfloat16 g_wv_h[(size_t)512 * 2048];
__device__ __align__(16) __nv_bfloat16 g_wv_l[(size_t)512 * 2048];
__device__ __align__(16) __nv_bfloat16 g_wo_h[(size_t)2048 * 4096];
__device__ __align__(16) __nv_bfloat16 g_wo_l[(size_t)2048 * 4096];
__device__ __align__(16) __nv_bfloat16 g_wg_h[(size_t)E_ * F_ * D_];
__device__ __align__(16) __nv_bfloat16 g_wg_l[(size_t)E_ * F_ * D_];
__device__ __align__(16) __nv_bfloat16 g_wu_h[(size_t)E_ * F_ * D_];
__device__ __align__(16) __nv_bfloat16 g_wu_l[(size_t)E_ * F_ * D_];
__device__ __align__(16) __nv_bfloat16 g_wd_h[(size_t)E_ * D_ * F_];
__device__ __align__(16) __nv_bfloat16 g_wd_l[(size_t)E_ * D_ * F_];

__device__ __forceinline__ float* buf_ptr(int id) {
    switch (id) {
        case 0: return g_hnorm;
        case 1: return g_q;
        case 2: return g_k;
        case 3: return g_v;
        case 4: return g_attn;
        case 5: return g_attnproj;
        case 6: return g_h2;
        case 7: return g_logits;
        case 8: return g_gate;
        case 9: return g_up;
        default: return g_ye;
    }
}
__device__ __forceinline__ __nv_bfloat16* bsel(int id, int hi) {
    switch (id) {
        case 0: return hi ? g_wq_h : g_wq_l;
        case 1: return hi ? g_wk_h : g_wk_l;
        case 2: return hi ? g_wv_h : g_wv_l;
        case 3: return hi ? g_wo_h : g_wo_l;
        case 4: return hi ? g_wg_h : g_wg_l;
        case 5: return hi ? g_wu_h : g_wu_l;
        default: return hi ? g_wd_h : g_wd_l;
    }
}
__device__ __forceinline__ __nv_bfloat16* asel(int id, int hi) {
    switch (id) {
        case 0: return hi ? g_a0h : g_a0l;
        case 1: return hi ? g_a1h : g_a1l;
        case 2: return hi ? g_a2h : g_a2l;
        default: return hi ? g_a3h : g_a3l;
    }
}
__device__ __forceinline__ void split2(float v, __nv_bfloat16* h, __nv_bfloat16* l) {
    __nv_bfloat16 hh = __float2bfloat16(v);
    *h = hh;
    *l = __float2bfloat16(v - __bfloat162float(hh));
}

__device__ __forceinline__ uint32_t smem_u32(const void* p) {
    uint32_t a;
    asm("{ .reg .u64 t; cvta.to.shared.u64 t, %1; cvt.u32.u64 %0, t; }" : "=r"(a) : "l"(p));
    return a;
}
#define CP16(d, s) asm volatile("cp.async.cg.shared.global [%0], [%1], 16;" :: "r"(d), "l"(s) : "memory")
#define MMA_BF16(c, a, b0, b1) \
    asm volatile("mma.sync.aligned.m16n8k16.row.col.f32.bf16.bf16.f32 " \
        "{%0,%1,%2,%3}, {%4,%5,%6,%7}, {%8,%9}, {%0,%1,%2,%3};" \
        : "+f"((c)[0]), "+f"((c)[1]), "+f"((c)[2]), "+f"((c)[3]) \
        : "r"((a)[0]), "r"((a)[1]), "r"((a)[2]), "r"((a)[3]), "r"(b0), "r"(b1))

// SMEM: 2 stages x 4 matrices x 128 rows x 80B (32 bf16 + pad)
#define MATB 10240
#define STGB 40960
#define SM_TOTAL 81920

// ---------------- convert + transpose: fp32 [K,N] -> bf16 hi/lo [N,K] ----------------
__global__ void convsplit_kernel(const float* __restrict__ W, int oid, int K, int N) {
    __shared__ float t[32][33];
    long base = (long)blockIdx.z * K * N;
    int kb = blockIdx.y * 32, nb = blockIdx.x * 32;
    int tx = threadIdx.x, ty = threadIdx.y;  // 32 x 8
    __nv_bfloat16* Oh = bsel(oid, 1);
    __nv_bfloat16* Ol = bsel(oid, 0);
#pragma unroll
    for (int j = 0; j < 4; j++)
        t[ty + j * 8][tx] = W[base + (long)(kb + ty + j * 8) * N + nb + tx];
    __syncthreads();
#pragma unroll
    for (int j = 0; j < 4; j++) {
        int r = ty + j * 8;
        float v = t[tx][r];
        long o = base + (long)(nb + r) * K + kb + tx;
        split2(v, Oh + o, Ol + o);
    }
}

// ---------------- HMMA bf16x3 GEMM: C[row,0:N) = A[arow,:] @ B_e[n,:]^T ----------------
// A: bf16 hi/lo [*,K] row-major; B: bf16 hi/lo [N,K] K-major; C fp32.
__global__ void __launch_bounds__(256, 2) mma_gemm(
    int aid, int bid, int cid, int segid, int usemap, int K, int Ntot, long wstride) {
    extern __shared__ char sm[];
    const int* seg = segid ? g_off : g_segT;
    int e = blockIdx.z;
    int segs = seg[e], sege = seg[e + 1];
    int m0 = segs + blockIdx.y * 128;
    if (m0 >= sege) return;
    int n0 = blockIdx.x * 128;
    const __nv_bfloat16* Ah = asel(aid, 1);
    const __nv_bfloat16* Al = asel(aid, 0);
    const __nv_bfloat16* Bh = bsel(bid, 1) + (long)e * wstride;
    const __nv_bfloat16* Bl = bsel(bid, 0) + (long)e * wstride;
    float* C = buf_ptr(cid);

    int tid = threadIdx.x;
    int lane = tid & 31, wid = tid >> 5;
    int gid = lane >> 2, tg = lane & 3;
    int m_off = (wid & 3) * 32, n_off = (wid >> 2) * 64;

    // prefetch assignment: thread covers rows r and r+64 of all four matrices, 16B chunk c16
    int r = tid >> 2, c16 = tid & 3;
    int gr0 = m0 + r;      if (gr0 > sege - 1) gr0 = sege - 1;
    int gr1 = m0 + r + 64; if (gr1 > sege - 1) gr1 = sege - 1;
    long a0off = (long)(usemap ? g_ptok[gr0] : gr0) * K + c16 * 8;
    long a1off = (long)(usemap ? g_ptok[gr1] : gr1) * K + c16 * 8;
    long b0off = (long)(n0 + r) * K + c16 * 8;
    long b1off = (long)(n0 + r + 64) * K + c16 * 8;
    uint32_t sb = smem_u32(sm);
    uint32_t d0 = sb + (uint32_t)(r * 80 + c16 * 16);
    uint32_t d1 = sb + (uint32_t)((r + 64) * 80 + c16 * 16);

    float acc[2][8][4];
#pragma unroll
    for (int mt = 0; mt < 2; mt++)
#pragma unroll
        for (int nt = 0; nt < 8; nt++)
#pragma unroll
            for (int j = 0; j < 4; j++) acc[mt][nt][j] = 0.f;

    auto prefetch = [&](int buf, int k0) {
        uint32_t s = (uint32_t)buf * STGB;
        CP16(d0 + s, Ah + a0off + k0);
        CP16(d1 + s, Ah + a1off + k0);
        CP16(d0 + s + MATB, Al + a0off + k0);
        CP16(d1 + s + MATB, Al + a1off + k0);
        CP16(d0 + s + 2 * MATB, Bh + b0off + k0);
        CP16(d1 + s + 2 * MATB, Bh + b1off + k0);
        CP16(d0 + s + 3 * MATB, Bl + b0off + k0);
        CP16(d1 + s + 3 * MATB, Bl + b1off + k0);
        asm volatile("cp.async.commit_group;" ::: "memory");
    };

    int nk = K / 32;
    prefetch(0, 0);
    for (int kc = 0; kc < nk; kc++) {
        if (kc + 1 < nk) {
            prefetch((kc + 1) & 1, (kc + 1) * 32);
            asm volatile("cp.async.wait_group 1;" ::: "memory");
        } else {
            asm volatile("cp.async.wait_group 0;" ::: "memory");
        }
        __syncthreads();
        const char* base = sm + (kc & 1) * STGB;
#pragma unroll
        for (int ks = 0; ks < 2; ks++) {
            int kb = ks * 16;  // element offset within 32-wide stage
            uint32_t a_h[2][4], a_l[2][4];
#pragma unroll
            for (int mt = 0; mt < 2; mt++) {
                const char* pa = base + (m_off + mt * 16 + gid) * 80 + (kb + tg * 2) * 2;
                a_h[mt][0] = *(const uint32_t*)(pa);
                a_h[mt][1] = *(const uint32_t*)(pa + 8 * 80);
                a_h[mt][2] = *(const uint32_t*)(pa + 16);
                a_h[mt][3] = *(const uint32_t*)(pa + 8 * 80 + 16);
                a_l[mt][0] = *(const uint32_t*)(pa + MATB);
                a_l[mt][1] = *(const uint32_t*)(pa + MATB + 8 * 80);
                a_l[mt][2] = *(const uint32_t*)(pa + MATB + 16);
                a_l[mt][3] = *(const uint32_t*)(pa + MATB + 8 * 80 + 16);
            }
#pragma unroll
            for (int nt = 0; nt < 8; nt++) {
                const char* pb = base + 2 * MATB + (n_off + nt * 8 + gid) * 80 + (kb + tg * 2) * 2;
                uint32_t bh0 = *(const uint32_t*)(pb);
                uint32_t bh1 = *(const uint32_t*)(pb + 16);
                uint32_t bl0 = *(const uint32_t*)(pb + MATB);
                uint32_t bl1 = *(const uint32_t*)(pb + MATB + 16);
#pragma unroll
                for (int mt = 0; mt < 2; mt++) {
                    MMA_BF16(acc[mt][nt], a_h[mt], bh0, bh1);
                    MMA_BF16(acc[mt][nt], a_h[mt], bl0, bl1);
                    MMA_BF16(acc[mt][nt], a_l[mt], bh0, bh1);
                }
            }
        }
        __syncthreads();
    }

    // epilogue
#pragma unroll
    for (int mt = 0; mt < 2; mt++) {
        int row = m0 + m_off + mt * 16 + gid;
#pragma unroll
        for (int nt = 0; nt < 8; nt++) {
            int col = n0 + n_off + nt * 8 + tg * 2;
            if (row < sege)
                *(float2*)(C + (long)row * Ntot + col) = make_float2(acc[mt][nt][0], acc[mt][nt][1]);
            if (row + 8 < sege)
                *(float2*)(C + (long)(row + 8) * Ntot + col) = make_float2(acc[mt][nt][2], acc[mt][nt][3]);
        }
    }
}

// ---------------- rmsnorm over D=2048: fp32 out + bf16 hi/lo pair ----------------
__global__ void rmsnorm_kernel(const float* __restrict__ xext, int oid, int pairid,
                               const float* __restrict__ scale) {
    const float* x = xext ? xext : g_res;
    float* out = buf_ptr(oid);
    __nv_bfloat16* ph = asel(pairid, 1);
    __nv_bfloat16* pl = asel(pairid, 0);
    int t = blockIdx.x;
    int tid = threadIdx.x;
    const float* xr = x + (size_t)t * D_;
    float v[8];
    float ss = 0.f;
#pragma unroll
    for (int j = 0; j < 8; j++) { v[j] = xr[tid + j * 256]; ss += v[j] * v[j]; }
#pragma unroll
    for (int o = 16; o; o >>= 1) ss += __shfl_xor_sync(0xffffffffu, ss, o);
    __shared__ float ws[8];
    if ((tid & 31) == 0) ws[tid >> 5] = ss;
    __syncthreads();
    float tot = 0.f;
#pragma unroll
    for (int w = 0; w < 8; w++) tot += ws[w];
    float inv = rsqrtf(tot / (float)D_ + 1e-6f);
    size_t rb = (size_t)t * D_;
#pragma unroll
    for (int j = 0; j < 8; j++) {
        int c = tid + j * 256;
        float y = v[j] * inv * scale[c];
        out[rb + c] = y;
        split2(y, ph + rb + c, pl + rb + c);
    }
}

// ---------------- fp32 SIMT GEMM (router only) ----------------
__global__ void __launch_bounds__(256) gemm_kernel(
    int xid, const float* __restrict__ W, int cid,
    int segid, int usemap, int K, int N, long wstride) {
    const int* seg = segid ? g_off : g_segT;
    int e = blockIdx.z;
    int segs = seg[e], sege = seg[e + 1];
    int m0 = segs + blockIdx.y * 128;
    if (m0 >= sege) return;
    const float* X = buf_ptr(xid);
    float* C = buf_ptr(cid);
    const float* Wp = W + (long)e * wstride;
    int n0 = blockIdx.x * 128;

    __shared__ float As[8][132];
    __shared__ float Bs[8][128];

    int tid = threadIdx.x;
    int am = tid >> 1, ak = (tid & 1) * 4;
    int bk = tid >> 5, bn = (tid & 31) * 4;
    int tx = tid & 15, ty = tid >> 4;

    int gr = m0 + am;
    bool avalid = gr < sege;
    int arow = avalid ? (usemap ? g_ptok[gr] : gr) : 0;
    const float* ap = X + (long)arow * K + ak;
    const float* bp = Wp + (long)bk * N + n0 + bn;
    bool bvalid = (n0 + bn) < N;

    float acc[8][8];
#pragma unroll
    for (int i = 0; i < 8; i++)
#pragma unroll
        for (int j = 0; j < 8; j++) acc[i][j] = 0.f;

    for (int k0 = 0; k0 < K; k0 += 8) {
        float4 a4 = avalid ? *(const float4*)(ap + k0) : make_float4(0, 0, 0, 0);
        float4 b4 = bvalid ? *(const float4*)(bp + (long)k0 * N) : make_float4(0, 0, 0, 0);
        __syncthreads();
        As[ak + 0][am] = a4.x;
        As[ak + 1][am] = a4.y;
        As[ak + 2][am] = a4.z;
        As[ak + 3][am] = a4.w;
        *(float4*)&Bs[bk][bn] = b4;
        __syncthreads();
#pragma unroll
        for (int kk = 0; kk < 8; kk++) {
            float ar[8], br[8];
            *(float4*)&ar[0] = *(const float4*)&As[kk][ty * 8];
            *(float4*)&ar[4] = *(const float4*)&As[kk][ty * 8 + 4];
            *(float4*)&br[0] = *(const float4*)&Bs[kk][tx * 8];
            *(float4*)&br[4] = *(const float4*)&Bs[kk][tx * 8 + 4];
#pragma unroll
            for (int i = 0; i < 8; i++)
#pragma unroll
                for (int j = 0; j < 8; j++) acc[i][j] += ar[i] * br[j];
        }
    }
    bool cn = (n0 + tx * 8) < N;
#pragma unroll
    for (int i = 0; i < 8; i++) {
        int row = m0 + ty * 8 + i;
        if (row < sege && cn) {
            float* cp = C + (long)row * N + n0 + tx * 8;
            *(float4*)cp = make_float4(acc[i][0], acc[i][1], acc[i][2], acc[i][3]);
            *(float4*)(cp + 4) = make_float4(acc[i][4], acc[i][5], acc[i][6], acc[i][7]);
        }
    }
}

// ---------------- per-head rmsnorm (HD=128) + RoPE, in place ----------------
__global__ void qknorm_rope_kernel(int bid, const int* __restrict__ positions,
                                   const float* __restrict__ sc, int H) {
    float* buf = buf_ptr(bid);
    int t = blockIdx.x, h = blockIdx.y;
    float* x = buf + ((size_t)t * H + h) * HD_;
    int d = threadIdx.x;
    float v = x[d];
    float sq = v * v;
#pragma unroll
    for (int o = 16; o; o >>= 1) sq += __shfl_xor_sync(0xffffffffu, sq, o);
    __shared__ float ws[4];
    __shared__ float sh[HD_];
    if ((d & 31) == 0) ws[d >> 5] = sq;
    __syncthreads();
    float tot = ws[0] + ws[1] + ws[2] + ws[3];
    float xn = v * rsqrtf(tot / 128.f + 1e-6f) * sc[d];
    sh[d] = xn;
    __syncthreads();
    if (d < 64) {
        double invf = exp(-13.815510557964274 * ((double)d / 64.0));
        double ang = (double)positions[t] * invf;
        float c = (float)cos(ang);
        float s = (float)sin(ang);
        float x1 = sh[d], x2 = sh[d + 64];
        x[d] = x1 * c - x2 * s;
        x[d + 64] = x2 * c + x1 * s;
    }
}

// ---------------- causal flash attention ----------------
__global__ void __launch_bounds__(128) attn_kernel() {
    int hq = blockIdx.y;
    int kv = hq >> 3;
    int q0 = blockIdx.x * 32;
    int tid = threadIdx.x;
    int r = tid >> 2, dq = tid & 3;
    const float* qp = g_q + ((size_t)(q0 + r) * HQ_ + hq) * HD_ + dq * 32;
    float q[32], o[32];
#pragma unroll
    for (int i = 0; i < 32; i++) { q[i] = qp[i]; o[i] = 0.f; }
    float m = -INFINITY, l = 0.f;
    __shared__ float Ks[32][HD_];
    __shared__ float Vs[32][HD_];
    const float scale = 0.08838834764831845f;

    for (int c0 = 0; c0 <= q0 + 31; c0 += 32) {
        __syncthreads();
        for (int idx = tid; idx < 32 * HD_; idx += 128) {
            int row = idx >> 7, col = idx & 127;
            Ks[row][col] = g_k[((size_t)(c0 + row) * HKV_ + kv) * HD_ + col];
            Vs[row][col] = g_v[((size_t)(c0 + row) * HKV_ + kv) * HD_ + col];
        }
        __syncthreads();
        float s[32];
        float tmax = -INFINITY;
#pragma unroll
        for (int c = 0; c < 32; c++) {
            float p = 0.f;
#pragma unroll
            for (int i = 0; i < 32; i++) p += q[i] * Ks[c][dq * 32 + i];
            p += __shfl_xor_sync(0xffffffffu, p, 1);
            p += __shfl_xor_sync(0xffffffffu, p, 2);
            p *= scale;
            if (c0 + c > q0 + r) p = -INFINITY;
            s[c] = p;
            tmax = fmaxf(tmax, p);
        }
        float mnew = fmaxf(m, tmax);
        float corr = __expf(m - mnew);
        l *= corr;
#pragma unroll
        for (int i = 0; i < 32; i++) o[i] *= corr;
#pragma unroll
        for (int c = 0; c < 32; c++) {
            float p = __expf(s[c] - mnew);
            l += p;
#pragma unroll
            for (int i = 0; i < 32; i++) o[i] += p * Vs[c][dq * 32 + i];
        }
        m = mnew;
    }
    float invl = 1.f / l;
    float* op = g_attn + ((size_t)(q0 + r) * HQ_ + hq) * HD_ + dq * 32;
#pragma unroll
    for (int i = 0; i < 32; i++) op[i] = o[i] * invl;
}

// ---------------- split attn output into bf16 hi/lo ----------------
__global__ void split_attn_kernel() {
    for (int i = blockIdx.x * 256 + threadIdx.x; i < T_ * HQ_ * HD_; i += gridDim.x * 256)
        split2(g_attn[i], g_a1h + i, g_a1l + i);
}

// ---------------- residual add ----------------
__global__ void resadd_kernel(const float* __restrict__ hidden, float* __restrict__ outres) {
    for (int i = blockIdx.x * 256 + threadIdx.x; i < T_ * D_; i += gridDim.x * 256) {
        float r = g_attnproj[i] + hidden[i];
        g_res[i] = r;
        outres[i] = r;
    }
}

// ---------------- router top-k ----------------
__global__ void topk_kernel() {
    int t = blockIdx.x * 8 + (threadIdx.x >> 5);
    int lane = threadIdx.x & 31;
    const float* lg = g_logits + (size_t)t * E_;
    float v0 = lg[lane], v1 = lg[lane + 32];
    float mx = fmaxf(v0, v1);
#pragma unroll
    for (int o = 16; o; o >>= 1) mx = fmaxf(mx, __shfl_xor_sync(0xffffffffu, mx, o));
    float e0 = expf(v0 - mx), e1 = expf(v1 - mx);
    float ssum = e0 + e1;
#pragma unroll
    for (int o = 16; o; o >>= 1) ssum += __shfl_xor_sync(0xffffffffu, ssum, o);
    float p0 = e0 / ssum, p1 = e1 / ssum;
    float selv[TOPK_];
    int seli[TOPK_];
#pragma unroll
    for (int it = 0; it < TOPK_; it++) {
        float bv; int bi;
        if (p0 >= p1) { bv = p0; bi = lane; } else { bv = p1; bi = lane + 32; }
#pragma unroll
        for (int o = 16; o; o >>= 1) {
            float ov = __shfl_xor_sync(0xffffffffu, bv, o);
            int oi = __shfl_xor_sync(0xffffffffu, bi, o);
            if (ov > bv || (ov == bv && oi < bi)) { bv = ov; bi = oi; }
        }
        selv[it] = bv;
        seli[it] = bi;
        if (bi == lane) p0 = -1.f;
        if (bi == lane + 32) p1 = -1.f;
    }
    float tot = 0.f;
#pragma unroll
    for (int it = 0; it < TOPK_; it++) tot += selv[it];
    if (lane == 0) {
#pragma unroll
        for (int it = 0; it < TOPK_; it++) {
            g_topv[t * TOPK_ + it] = selv[it] / tot;
            g_topi[t * TOPK_ + it] = seli[it];
        }
    }
}

// ---------------- MoE routing bookkeeping ----------------
__global__ void zero_kernel() {
    int i = threadIdx.x;
    if (i < E_) { g_cnt[i] = 0; g_cur[i] = 0; }
}
__global__ void count_kernel() {
    int i = blockIdx.x * 256 + threadIdx.x;
    if (i < NTOK) atomicAdd(&g_cnt[g_topi[i]], 1);
}
__global__ void scan_kernel() {
    if (threadIdx.x == 0) {
        int a = 0;
        for (int e = 0; e < E_; e++) { g_off[e] = a; a += g_cnt[e]; }
        g_off[E_] = a;
    }
}
__global__ void assign_kernel() {
    int i = blockIdx.x * 256 + threadIdx.x;
    if (i < NTOK) {
        int e = g_topi[i];
        int r = g_off[e] + atomicAdd(&g_cur[e], 1);
        g_ptok[r] = i >> 3;
        g_rowof[i] = r;
    }
}

// ---------------- silu(gate) * up -> bf16 hi/lo ----------------
__global__ void silu_mul_kernel() {
    for (int i = blockIdx.x * 256 + threadIdx.x; i < NTOK * F_; i += gridDim.x * 256) {
        float g = g_gate[i];
        float u = g_up[i];
        float y = g / (1.f + __expf(-g)) * u;
        split2(y, g_a3h + i, g_a3l + i);
    }
}

// ---------------- combine expert outputs ----------------
__global__ void combine_kernel(float* __restrict__ out) {
    int t = blockIdx.x;
    float w[TOPK_];
    int rw[TOPK_];
#pragma unroll
    for (int j = 0; j < TOPK_; j++) {
        w[j] = g_topv[t * TOPK_ + j];
        rw[j] = g_rowof[t * TOPK_ + j];
    }
    for (int d = threadIdx.x; d < D_; d += 256) {
        float acc = 0.f;
#pragma unroll
        for (int j = 0; j < TOPK_; j++)
            acc += w[j] * g_ye[(size_t)rw[j] * D_ + d];
        out[(size_t)t * D_ + d] = acc;
    }
}

// ---------------- launch ----------------
extern "C" void kernel_launch(void* const* d_in, const int* in_sizes, int n_in,
                              void* d_out, int out_size) {
    const int* positions = (const int*)d_in[0];
    const float* hidden = (const float*)d_in[1];
    const float* in_ln = (const float*)d_in[2];
    const float* post_ln = (const float*)d_in[3];
    const float* qns = (const float*)d_in[4];
    const float* kns = (const float*)d_in[5];
    const float* wq = (const float*)d_in[6];
    const float* wk = (const float*)d_in[7];
    const float* wv = (const float*)d_in[8];
    const float* wo = (const float*)d_in[9];
    const float* wr = (const float*)d_in[10];
    const float* wg = (const float*)d_in[11];
    const float* wu = (const float*)d_in[12];
    const float* wd = (const float*)d_in[13];
    float* out = (float*)d_out;

    static int smem_set = 0;
    if (!smem_set) {
        cudaFuncSetAttribute(mma_gemm, cudaFuncAttributeMaxDynamicSharedMemorySize, SM_TOTAL);
        smem_set = 1;
    }
    dim3 cb(32, 8);

    // weight convert + transpose (bf16 hi/lo, [N,K])
    convsplit_kernel<<<dim3(4096 / 32, 2048 / 32, 1), cb>>>(wq, 0, 2048, 4096);
    convsplit_kernel<<<dim3(512 / 32, 2048 / 32, 1), cb>>>(wk, 1, 2048, 512);
    convsplit_kernel<<<dim3(512 / 32, 2048 / 32, 1), cb>>>(wv, 2, 2048, 512);
    convsplit_kernel<<<dim3(2048 / 32, 4096 / 32, 1), cb>>>(wo, 3, 4096, 2048);
    convsplit_kernel<<<dim3(768 / 32, 2048 / 32, 64), cb>>>(wg, 4, 2048, 768);
    convsplit_kernel<<<dim3(768 / 32, 2048 / 32, 64), cb>>>(wu, 5, 2048, 768);
    convsplit_kernel<<<dim3(2048 / 32, 768 / 32, 64), cb>>>(wd, 6, 768, 2048);

    // pre-attention norm + QKV projections (HMMA bf16x3)
    rmsnorm_kernel<<<T_, 256>>>(hidden, 0, 0, in_ln);
    mma_gemm<<<dim3(32, 16, 1), 256, SM_TOTAL>>>(0, 0, 1, 0, 0, D_, HQ_ * HD_, 0);
    mma_gemm<<<dim3(4, 16, 1), 256, SM_TOTAL>>>(0, 1, 2, 0, 0, D_, HKV_ * HD_, 0);
    mma_gemm<<<dim3(4, 16, 1), 256, SM_TOTAL>>>(0, 2, 3, 0, 0, D_, HKV_ * HD_, 0);
    // per-head rmsnorm + rope
    qknorm_rope_kernel<<<dim3(T_, HQ_), HD_>>>(1, positions, qns, HQ_);
    qknorm_rope_kernel<<<dim3(T_, HKV_), HD_>>>(2, positions, kns, HKV_);
    // causal attention + output projection + residual
    attn_kernel<<<dim3(T_ / 32, HQ_), 128>>>();
    split_attn_kernel<<<4096, 256>>>();
    mma_gemm<<<dim3(16, 16, 1), 256, SM_TOTAL>>>(1, 3, 5, 0, 0, HQ_ * HD_, D_, 0);
    resadd_kernel<<<2048, 256>>>(hidden, out + (size_t)T_ * D_);
    // post-attention norm + router (exact fp32) + top-k
    rmsnorm_kernel<<<T_, 256>>>(nullptr, 6, 2, post_ln);
    gemm_kernel<<<dim3(1, 16, 1), 256>>>(6, wr, 7, 0, 0, D_, E_, 0);
    topk_kernel<<<T_ / 8, 256>>>();
    // expert grouping
    zero_kernel<<<1, 64>>>();
    count_kernel<<<NTOK / 256, 256>>>();
    scan_kernel<<<1, 32>>>();
    assign_kernel<<<NTOK / 256, 256>>>();
    // expert GEMMs (HMMA, grouped, gathered)
    mma_gemm<<<dim3(6, 24, 64), 256, SM_TOTAL>>>(2, 4, 8, 1, 1, D_, F_, (long)F_ * D_);
    mma_gemm<<<dim3(6, 24, 64), 256, SM_TOTAL>>>(2, 5, 9, 1, 1, D_, F_, (long)F_ * D_);
    silu_mul_kernel<<<8192, 256>>>();
    mma_gemm<<<dim3(16, 24, 64), 256, SM_TOTAL>>>(3, 6, 10, 1, 0, F_, D_, (long)D_ * F_);
    combine_kernel<<<T_, 256>>>(out);
}

// round 9
// speedup vs baseline: 4.3549x; 3.0517x over previous
#include <cuda_runtime.h>
#include <cuda_bf16.h>
#include <math.h>
#include <stdint.h>

#define T_    2048
#define D_    2048
#define HQ_   32
#define HKV_  4
#define HD_   128
#define E_    64
#define TOPK_ 8
#define F_    768
#define NTOK  (T_ * TOPK_)

// ---------------- scratch (static device globals; no allocation) ----------------
__device__ float g_hnorm[T_ * D_];
__device__ float g_q[T_ * HQ_ * HD_];
__device__ float g_k[T_ * HKV_ * HD_];
__device__ float g_v[T_ * HKV_ * HD_];
__device__ float g_attn[T_ * HQ_ * HD_];   // unused (kept for buf ids)
__device__ float g_attnproj[T_ * D_];
__device__ float g_res[T_ * D_];
__device__ float g_h2[T_ * D_];
__device__ float g_logits[T_ * E_];
__device__ float g_topv[NTOK];
__device__ int   g_topi[NTOK];
__device__ int   g_cnt[E_];
__device__ int   g_cur[E_];
__device__ int   g_off[E_ + 1];
__device__ int   g_ptok[NTOK];
__device__ int   g_rowof[NTOK];
__device__ float g_gate[NTOK * F_];
__device__ float g_up[NTOK * F_];
__device__ float g_ye[(size_t)NTOK * D_];
__device__ int   g_segT[2] = {0, T_};
__device__ float g_rcos[T_ * 64];
__device__ float g_rsin[T_ * 64];

// activation hi/lo bf16 buffers
__device__ __align__(16) __nv_bfloat16 g_a0h[T_ * D_];            // hnorm
__device__ __align__(16) __nv_bfloat16 g_a0l[T_ * D_];
__device__ __align__(16) __nv_bfloat16 g_a1h[T_ * HQ_ * HD_];     // attn out
__device__ __align__(16) __nv_bfloat16 g_a1l[T_ * HQ_ * HD_];
__device__ __align__(16) __nv_bfloat16 g_a2h[T_ * D_];            // h2
__device__ __align__(16) __nv_bfloat16 g_a2l[T_ * D_];
__device__ __align__(16) __nv_bfloat16 g_a3h[(size_t)NTOK * F_];  // silu*up
__device__ __align__(16) __nv_bfloat16 g_a3l[(size_t)NTOK * F_];

// transposed bf16 hi/lo weight copies ([N,K] K-major per expert)
__device__ __align__(16) __nv_bfloat16 g_wq_h[(size_t)4096 * 2048];
__device__ __align__(16) __nv_bfloat16 g_wq_l[(size_t)4096 * 2048];
__device__ __align__(16) __nv_bfloat16 g_wk_h[(size_t)512 * 2048];
__device__ __align__(16) __nv_bfloat16 g_wk_l[(size_t)512 * 2048];
__device__ __align__(16) __nv_bfloat16 g_wv_h[(size_t)512 * 2048];
__device__ __align__(16) __nv_bfloat16 g_wv_l[(size_t)512 * 2048];
__device__ __align__(16) __nv_bfloat16 g_wo_h[(size_t)2048 * 4096];
__device__ __align__(16) __nv_bfloat16 g_wo_l[(size_t)2048 * 4096];
__device__ __align__(16) __nv_bfloat16 g_wg_h[(size_t)E_ * F_ * D_];
__device__ __align__(16) __nv_bfloat16 g_wg_l[(size_t)E_ * F_ * D_];
__device__ __align__(16) __nv_bfloat16 g_wu_h[(size_t)E_ * F_ * D_];
__device__ __align__(16) __nv_bfloat16 g_wu_l[(size_t)E_ * F_ * D_];
__device__ __align__(16) __nv_bfloat16 g_wd_h[(size_t)E_ * D_ * F_];
__device__ __align__(16) __nv_bfloat16 g_wd_l[(size_t)E_ * D_ * F_];

__device__ __forceinline__ float* buf_ptr(int id) {
    switch (id) {
        case 0: return g_hnorm;
        case 1: return g_q;
        case 2: return g_k;
        case 3: return g_v;
        case 4: return g_attn;
        case 5: return g_attnproj;
        case 6: return g_h2;
        case 7: return g_logits;
        case 8: return g_gate;
        case 9: return g_up;
        default: return g_ye;
    }
}
__device__ __forceinline__ __nv_bfloat16* bsel(int id, int hi) {
    switch (id) {
        case 0: return hi ? g_wq_h : g_wq_l;
        case 1: return hi ? g_wk_h : g_wk_l;
        case 2: return hi ? g_wv_h : g_wv_l;
        case 3: return hi ? g_wo_h : g_wo_l;
        case 4: return hi ? g_wg_h : g_wg_l;
        case 5: return hi ? g_wu_h : g_wu_l;
        default: return hi ? g_wd_h : g_wd_l;
    }
}
__device__ __forceinline__ __nv_bfloat16* asel(int id, int hi) {
    switch (id) {
        case 0: return hi ? g_a0h : g_a0l;
        case 1: return hi ? g_a1h : g_a1l;
        case 2: return hi ? g_a2h : g_a2l;
        default: return hi ? g_a3h : g_a3l;
    }
}
__device__ __forceinline__ void split2(float v, __nv_bfloat16* h, __nv_bfloat16* l) {
    __nv_bfloat16 hh = __float2bfloat16(v);
    *h = hh;
    *l = __float2bfloat16(v - __bfloat162float(hh));
}

__device__ __forceinline__ uint32_t smem_u32(const void* p) {
    uint32_t a;
    asm("{ .reg .u64 t; cvta.to.shared.u64 t, %1; cvt.u32.u64 %0, t; }" : "=r"(a) : "l"(p));
    return a;
}
#define CP16(d, s) asm volatile("cp.async.cg.shared.global [%0], [%1], 16;" :: "r"(d), "l"(s) : "memory")
#define MMA_BF16(c, a, b0, b1) \
    asm volatile("mma.sync.aligned.m16n8k16.row.col.f32.bf16.bf16.f32 " \
        "{%0,%1,%2,%3}, {%4,%5,%6,%7}, {%8,%9}, {%0,%1,%2,%3};" \
        : "+f"((c)[0]), "+f"((c)[1]), "+f"((c)[2]), "+f"((c)[3]) \
        : "r"((a)[0]), "r"((a)[1]), "r"((a)[2]), "r"((a)[3]), "r"(b0), "r"(b1))

// SMEM for mma_gemm: 2 stages x 4 matrices x 128 rows x 80B
#define MATB 10240
#define STGB 40960
#define SM_TOTAL 81920

// ---------------- convert + transpose: fp32 [K,N] -> bf16 hi/lo [N,K] ----------------
__global__ void convsplit_kernel(const float* __restrict__ W, int oid, int K, int N) {
    __shared__ float t[32][33];
    long base = (long)blockIdx.z * (long)K * N;
    int kb = blockIdx.y * 32, nb = blockIdx.x * 32;
    int tx = threadIdx.x, ty = threadIdx.y;  // 32 x 8
    __nv_bfloat16* Oh = bsel(oid, 1);
    __nv_bfloat16* Ol = bsel(oid, 0);
#pragma unroll
    for (int j = 0; j < 4; j++)
        t[ty + j * 8][tx] = W[base + (long)(kb + ty + j * 8) * N + nb + tx];
    __syncthreads();
    int id = ty * 32 + tx;
#pragma unroll
    for (int j = 0; j < 2; j++) {
        int item = id + j * 256;
        int row = item >> 4, cp = item & 15;
        float v0 = t[2 * cp][row], v1 = t[2 * cp + 1][row];
        __nv_bfloat162 h = __floats2bfloat162_rn(v0, v1);
        float2 hf = __bfloat1622float2(h);
        __nv_bfloat162 l = __floats2bfloat162_rn(v0 - hf.x, v1 - hf.y);
        long o = base + (long)(nb + row) * K + kb + 2 * cp;
        *(uint32_t*)(Oh + o) = *(uint32_t*)&h;
        *(uint32_t*)(Ol + o) = *(uint32_t*)&l;
    }
}

// ---------------- HMMA bf16x3 GEMM ----------------
__global__ void __launch_bounds__(256, 2) mma_gemm(
    int aid, int bid, int cid, int segid, int usemap, int K, int Ntot, long wstride) {
    extern __shared__ char sm[];
    const int* seg = segid ? g_off : g_segT;
    int e = blockIdx.z;
    int segs = seg[e], sege = seg[e + 1];
    int m0 = segs + blockIdx.y * 128;
    if (m0 >= sege) return;
    int n0 = blockIdx.x * 128;
    const __nv_bfloat16* Ah = asel(aid, 1);
    const __nv_bfloat16* Al = asel(aid, 0);
    const __nv_bfloat16* Bh = bsel(bid, 1) + (long)e * wstride;
    const __nv_bfloat16* Bl = bsel(bid, 0) + (long)e * wstride;
    float* C = buf_ptr(cid);

    int tid = threadIdx.x;
    int lane = tid & 31, wid = tid >> 5;
    int gid = lane >> 2, tg = lane & 3;
    int m_off = (wid & 3) * 32, n_off = (wid >> 2) * 64;

    int r = tid >> 2, c16 = tid & 3;
    int gr0 = m0 + r;      if (gr0 > sege - 1) gr0 = sege - 1;
    int gr1 = m0 + r + 64; if (gr1 > sege - 1) gr1 = sege - 1;
    long a0off = (long)(usemap ? g_ptok[gr0] : gr0) * K + c16 * 8;
    long a1off = (long)(usemap ? g_ptok[gr1] : gr1) * K + c16 * 8;
    long b0off = (long)(n0 + r) * K + c16 * 8;
    long b1off = (long)(n0 + r + 64) * K + c16 * 8;
    uint32_t sb = smem_u32(sm);
    uint32_t d0 = sb + (uint32_t)(r * 80 + c16 * 16);
    uint32_t d1 = sb + (uint32_t)((r + 64) * 80 + c16 * 16);

    float acc[2][8][4];
#pragma unroll
    for (int mt = 0; mt < 2; mt++)
#pragma unroll
        for (int nt = 0; nt < 8; nt++)
#pragma unroll
            for (int j = 0; j < 4; j++) acc[mt][nt][j] = 0.f;

    auto prefetch = [&](int buf, int k0) {
        uint32_t s = (uint32_t)buf * STGB;
        CP16(d0 + s, Ah + a0off + k0);
        CP16(d1 + s, Ah + a1off + k0);
        CP16(d0 + s + MATB, Al + a0off + k0);
        CP16(d1 + s + MATB, Al + a1off + k0);
        CP16(d0 + s + 2 * MATB, Bh + b0off + k0);
        CP16(d1 + s + 2 * MATB, Bh + b1off + k0);
        CP16(d0 + s + 3 * MATB, Bl + b0off + k0);
        CP16(d1 + s + 3 * MATB, Bl + b1off + k0);
        asm volatile("cp.async.commit_group;" ::: "memory");
    };

    int nk = K / 32;
    prefetch(0, 0);
    for (int kc = 0; kc < nk; kc++) {
        if (kc + 1 < nk) {
            prefetch((kc + 1) & 1, (kc + 1) * 32);
            asm volatile("cp.async.wait_group 1;" ::: "memory");
        } else {
            asm volatile("cp.async.wait_group 0;" ::: "memory");
        }
        __syncthreads();
        const char* base = sm + (kc & 1) * STGB;
#pragma unroll
        for (int ks = 0; ks < 2; ks++) {
            int kb = ks * 16;
            uint32_t a_h[2][4], a_l[2][4];
#pragma unroll
            for (int mt = 0; mt < 2; mt++) {
                const char* pa = base + (m_off + mt * 16 + gid) * 80 + (kb + tg * 2) * 2;
                a_h[mt][0] = *(const uint32_t*)(pa);
                a_h[mt][1] = *(const uint32_t*)(pa + 8 * 80);
                a_h[mt][2] = *(const uint32_t*)(pa + 16);
                a_h[mt][3] = *(const uint32_t*)(pa + 8 * 80 + 16);
                a_l[mt][0] = *(const uint32_t*)(pa + MATB);
                a_l[mt][1] = *(const uint32_t*)(pa + MATB + 8 * 80);
                a_l[mt][2] = *(const uint32_t*)(pa + MATB + 16);
                a_l[mt][3] = *(const uint32_t*)(pa + MATB + 8 * 80 + 16);
            }
#pragma unroll
            for (int nt = 0; nt < 8; nt++) {
                const char* pb = base + 2 * MATB + (n_off + nt * 8 + gid) * 80 + (kb + tg * 2) * 2;
                uint32_t bh0 = *(const uint32_t*)(pb);
                uint32_t bh1 = *(const uint32_t*)(pb + 16);
                uint32_t bl0 = *(const uint32_t*)(pb + MATB);
                uint32_t bl1 = *(const uint32_t*)(pb + MATB + 16);
#pragma unroll
                for (int mt = 0; mt < 2; mt++) {
                    MMA_BF16(acc[mt][nt], a_h[mt], bh0, bh1);
                    MMA_BF16(acc[mt][nt], a_h[mt], bl0, bl1);
                    MMA_BF16(acc[mt][nt], a_l[mt], bh0, bh1);
                }
            }
        }
        __syncthreads();
    }

#pragma unroll
    for (int mt = 0; mt < 2; mt++) {
        int row = m0 + m_off + mt * 16 + gid;
#pragma unroll
        for (int nt = 0; nt < 8; nt++) {
            int col = n0 + n_off + nt * 8 + tg * 2;
            if (row < sege)
                *(float2*)(C + (long)row * Ntot + col) = make_float2(acc[mt][nt][0], acc[mt][nt][1]);
            if (row + 8 < sege)
                *(float2*)(C + (long)(row + 8) * Ntot + col) = make_float2(acc[mt][nt][2], acc[mt][nt][3]);
        }
    }
}

// ---------------- rmsnorm over D=2048: fp32 out + bf16 hi/lo pair ----------------
__global__ void rmsnorm_kernel(const float* __restrict__ xext, int oid, int pairid,
                               const float* __restrict__ scale) {
    const float* x = xext ? xext : g_res;
    float* out = buf_ptr(oid);
    __nv_bfloat16* ph = asel(pairid, 1);
    __nv_bfloat16* pl = asel(pairid, 0);
    int t = blockIdx.x;
    int tid = threadIdx.x;
    const float* xr = x + (size_t)t * D_;
    float v[8];
    float ss = 0.f;
#pragma unroll
    for (int j = 0; j < 8; j++) { v[j] = xr[tid + j * 256]; ss += v[j] * v[j]; }
#pragma unroll
    for (int o = 16; o; o >>= 1) ss += __shfl_xor_sync(0xffffffffu, ss, o);
    __shared__ float ws[8];
    if ((tid & 31) == 0) ws[tid >> 5] = ss;
    __syncthreads();
    float tot = 0.f;
#pragma unroll
    for (int w = 0; w < 8; w++) tot += ws[w];
    float inv = rsqrtf(tot / (float)D_ + 1e-6f);
    size_t rb = (size_t)t * D_;
#pragma unroll
    for (int j = 0; j < 8; j++) {
        int c = tid + j * 256;
        float y = v[j] * inv * scale[c];
        out[rb + c] = y;
        split2(y, ph + rb + c, pl + rb + c);
    }
}

// ---------------- fp32 SIMT GEMM (router only) ----------------
__global__ void __launch_bounds__(256) gemm_kernel(
    int xid, const float* __restrict__ W, int cid,
    int segid, int usemap, int K, int N, long wstride) {
    const int* seg = segid ? g_off : g_segT;
    int e = blockIdx.z;
    int segs = seg[e], sege = seg[e + 1];
    int m0 = segs + blockIdx.y * 128;
    if (m0 >= sege) return;
    const float* X = buf_ptr(xid);
    float* C = buf_ptr(cid);
    const float* Wp = W + (long)e * wstride;
    int n0 = blockIdx.x * 128;

    __shared__ float As[8][132];
    __shared__ float Bs[8][128];

    int tid = threadIdx.x;
    int am = tid >> 1, ak = (tid & 1) * 4;
    int bk = tid >> 5, bn = (tid & 31) * 4;
    int tx = tid & 15, ty = tid >> 4;

    int gr = m0 + am;
    bool avalid = gr < sege;
    int arow = avalid ? (usemap ? g_ptok[gr] : gr) : 0;
    const float* ap = X + (long)arow * K + ak;
    const float* bp = Wp + (long)bk * N + n0 + bn;
    bool bvalid = (n0 + bn) < N;

    float acc[8][8];
#pragma unroll
    for (int i = 0; i < 8; i++)
#pragma unroll
        for (int j = 0; j < 8; j++) acc[i][j] = 0.f;

    for (int k0 = 0; k0 < K; k0 += 8) {
        float4 a4 = avalid ? *(const float4*)(ap + k0) : make_float4(0, 0, 0, 0);
        float4 b4 = bvalid ? *(const float4*)(bp + (long)k0 * N) : make_float4(0, 0, 0, 0);
        __syncthreads();
        As[ak + 0][am] = a4.x;
        As[ak + 1][am] = a4.y;
        As[ak + 2][am] = a4.z;
        As[ak + 3][am] = a4.w;
        *(float4*)&Bs[bk][bn] = b4;
        __syncthreads();
#pragma unroll
        for (int kk = 0; kk < 8; kk++) {
            float ar[8], br[8];
            *(float4*)&ar[0] = *(const float4*)&As[kk][ty * 8];
            *(float4*)&ar[4] = *(const float4*)&As[kk][ty * 8 + 4];
            *(float4*)&br[0] = *(const float4*)&Bs[kk][tx * 8];
            *(float4*)&br[4] = *(const float4*)&Bs[kk][tx * 8 + 4];
#pragma unroll
            for (int i = 0; i < 8; i++)
#pragma unroll
                for (int j = 0; j < 8; j++) acc[i][j] += ar[i] * br[j];
        }
    }
    bool cn = (n0 + tx * 8) < N;
#pragma unroll
    for (int i = 0; i < 8; i++) {
        int row = m0 + ty * 8 + i;
        if (row < sege && cn) {
            float* cp = C + (long)row * N + n0 + tx * 8;
            *(float4*)cp = make_float4(acc[i][0], acc[i][1], acc[i][2], acc[i][3]);
            *(float4*)(cp + 4) = make_float4(acc[i][4], acc[i][5], acc[i][6], acc[i][7]);
        }
    }
}

// ---------------- rope table (double precision, once) ----------------
__global__ void rope_table_kernel(const int* __restrict__ positions) {
    int t = blockIdx.x, d = threadIdx.x;
    double invf = exp(-13.815510557964274 * ((double)d / 64.0));
    double ang = (double)positions[t] * invf;
    g_rcos[t * 64 + d] = (float)cos(ang);
    g_rsin[t * 64 + d] = (float)sin(ang);
}

// ---------------- per-head rmsnorm (HD=128) + RoPE, in place ----------------
__global__ void qknorm_rope_kernel(int bid, const float* __restrict__ sc, int H) {
    float* buf = buf_ptr(bid);
    int t = blockIdx.x, h = blockIdx.y;
    float* x = buf + ((size_t)t * H + h) * HD_;
    int d = threadIdx.x;
    float v = x[d];
    float sq = v * v;
#pragma unroll
    for (int o = 16; o; o >>= 1) sq += __shfl_xor_sync(0xffffffffu, sq, o);
    __shared__ float ws[4];
    __shared__ float sh[HD_];
    if ((d & 31) == 0) ws[d >> 5] = sq;
    __syncthreads();
    float tot = ws[0] + ws[1] + ws[2] + ws[3];
    float xn = v * rsqrtf(tot / 128.f + 1e-6f) * sc[d];
    sh[d] = xn;
    __syncthreads();
    if (d < 64) {
        float c = g_rcos[t * 64 + d];
        float s = g_rsin[t * 64 + d];
        float x1 = sh[d], x2 = sh[d + 64];
        x[d] = x1 * c - x2 * s;
        x[d + 64] = x2 * c + x1 * s;
    }
}

// ---------------- HMMA causal flash attention ----------------
// grid (T/64, HQ), block 128 (4 warps x 16 q-rows). k-tile = 32 cols.
#define AS_QH 0
#define AS_QL 17408
#define AS_KH 34816
#define AS_KL 43520
#define AS_VH 52224
#define AS_VL 62464
#define AS_TOT 72704

__global__ void __launch_bounds__(128) attn_kernel() {
    extern __shared__ char as_[];
    int hq = blockIdx.y, kvh = hq >> 3;
    int q0 = blockIdx.x * 64;
    int tid = threadIdx.x, lane = tid & 31, wid = tid >> 5;
    int gid = lane >> 2, tg = lane & 3;
    int m0w = wid * 16;
    const float qscale = 0.08838834764831845f;

    // stage Q (scaled, split hi/lo, padded rows of 272B)
    for (int idx = tid; idx < 64 * 32; idx += 128) {
        int r = idx >> 5, d = (idx & 31) * 4;
        float4 v = *(const float4*)(g_q + ((size_t)(q0 + r) * HQ_ + hq) * HD_ + d);
        v.x *= qscale; v.y *= qscale; v.z *= qscale; v.w *= qscale;
        __nv_bfloat162 h01 = __floats2bfloat162_rn(v.x, v.y);
        __nv_bfloat162 h23 = __floats2bfloat162_rn(v.z, v.w);
        float2 f01 = __bfloat1622float2(h01), f23 = __bfloat1622float2(h23);
        __nv_bfloat162 l01 = __floats2bfloat162_rn(v.x - f01.x, v.y - f01.y);
        __nv_bfloat162 l23 = __floats2bfloat162_rn(v.z - f23.x, v.w - f23.y);
        *(uint2*)(as_ + AS_QH + r * 272 + d * 2) = make_uint2(*(uint32_t*)&h01, *(uint32_t*)&h23);
        *(uint2*)(as_ + AS_QL + r * 272 + d * 2) = make_uint2(*(uint32_t*)&l01, *(uint32_t*)&l23);
    }
    __syncthreads();

    // Q fragments in registers (8 ksteps)
    uint32_t qh[8][4], ql[8][4];
#pragma unroll
    for (int ks = 0; ks < 8; ks++) {
        const char* pa = as_ + AS_QH + (m0w + gid) * 272 + (ks * 16 + tg * 2) * 2;
        qh[ks][0] = *(const uint32_t*)pa;
        qh[ks][1] = *(const uint32_t*)(pa + 8 * 272);
        qh[ks][2] = *(const uint32_t*)(pa + 16);
        qh[ks][3] = *(const uint32_t*)(pa + 8 * 272 + 16);
        const char* pl = pa + (AS_QL - AS_QH);
        ql[ks][0] = *(const uint32_t*)pl;
        ql[ks][1] = *(const uint32_t*)(pl + 8 * 272);
        ql[ks][2] = *(const uint32_t*)(pl + 16);
        ql[ks][3] = *(const uint32_t*)(pl + 8 * 272 + 16);
    }

    float oacc[16][4];
#pragma unroll
    for (int nt = 0; nt < 16; nt++)
#pragma unroll
        for (int j = 0; j < 4; j++) oacc[nt][j] = 0.f;
    float mA = -INFINITY, mB = -INFINITY, lA = 0.f, lB = 0.f;
    int rowA = q0 + m0w + gid, rowB = rowA + 8;

    int nkt = q0 / 32 + 2;
    for (int kt = 0; kt < nkt; kt++) {
        int c0 = kt * 32;
        __syncthreads();
        // stage K tile [32 kcols][128] hi/lo
        {
            int r = tid >> 2;
#pragma unroll
            for (int cc = 0; cc < 8; cc++) {
                int d = ((tid & 3) + cc * 4) * 4;
                float4 v = *(const float4*)(g_k + ((size_t)(c0 + r) * HKV_ + kvh) * HD_ + d);
                __nv_bfloat162 h01 = __floats2bfloat162_rn(v.x, v.y);
                __nv_bfloat162 h23 = __floats2bfloat162_rn(v.z, v.w);
                float2 f01 = __bfloat1622float2(h01), f23 = __bfloat1622float2(h23);
                __nv_bfloat162 l01 = __floats2bfloat162_rn(v.x - f01.x, v.y - f01.y);
                __nv_bfloat162 l23 = __floats2bfloat162_rn(v.z - f23.x, v.w - f23.y);
                *(uint2*)(as_ + AS_KH + r * 272 + d * 2) = make_uint2(*(uint32_t*)&h01, *(uint32_t*)&h23);
                *(uint2*)(as_ + AS_KL + r * 272 + d * 2) = make_uint2(*(uint32_t*)&l01, *(uint32_t*)&l23);
            }
        }
        // stage V transposed [128 d][32 kcols] hi/lo (rows padded to 80B)
        {
#pragma unroll
            for (int j = 0; j < 16; j++) {
                float v0 = g_v[((size_t)(c0 + 2 * j) * HKV_ + kvh) * HD_ + tid];
                float v1 = g_v[((size_t)(c0 + 2 * j + 1) * HKV_ + kvh) * HD_ + tid];
                __nv_bfloat162 h = __floats2bfloat162_rn(v0, v1);
                float2 hf = __bfloat1622float2(h);
                __nv_bfloat162 l = __floats2bfloat162_rn(v0 - hf.x, v1 - hf.y);
                *(uint32_t*)(as_ + AS_VH + tid * 80 + j * 4) = *(uint32_t*)&h;
                *(uint32_t*)(as_ + AS_VL + tid * 80 + j * 4) = *(uint32_t*)&l;
            }
        }
        __syncthreads();

        // S = Q @ K^T (bf16x3)
        float sacc[4][4];
#pragma unroll
        for (int nt = 0; nt < 4; nt++)
#pragma unroll
            for (int j = 0; j < 4; j++) sacc[nt][j] = 0.f;
#pragma unroll
        for (int ks = 0; ks < 8; ks++)
#pragma unroll
            for (int nt = 0; nt < 4; nt++) {
                const char* pb = as_ + AS_KH + (nt * 8 + gid) * 272 + (ks * 16 + tg * 2) * 2;
                uint32_t bh0 = *(const uint32_t*)pb;
                uint32_t bh1 = *(const uint32_t*)(pb + 16);
                const char* pbl = pb + (AS_KL - AS_KH);
                uint32_t bl0 = *(const uint32_t*)pbl;
                uint32_t bl1 = *(const uint32_t*)(pbl + 16);
                MMA_BF16(sacc[nt], qh[ks], bh0, bh1);
                MMA_BF16(sacc[nt], qh[ks], bl0, bl1);
                MMA_BF16(sacc[nt], ql[ks], bh0, bh1);
            }

        // causal mask
        if (c0 + 31 > rowA) {
#pragma unroll
            for (int nt = 0; nt < 4; nt++) {
                int cb = c0 + nt * 8 + tg * 2;
                if (cb > rowA) sacc[nt][0] = -1e30f;
                if (cb + 1 > rowA) sacc[nt][1] = -1e30f;
            }
        }
        if (c0 + 31 > rowB) {
#pragma unroll
            for (int nt = 0; nt < 4; nt++) {
                int cb = c0 + nt * 8 + tg * 2;
                if (cb > rowB) sacc[nt][2] = -1e30f;
                if (cb + 1 > rowB) sacc[nt][3] = -1e30f;
            }
        }

        // online softmax
        float mxA = -INFINITY, mxB = -INFINITY;
#pragma unroll
        for (int nt = 0; nt < 4; nt++) {
            mxA = fmaxf(mxA, fmaxf(sacc[nt][0], sacc[nt][1]));
            mxB = fmaxf(mxB, fmaxf(sacc[nt][2], sacc[nt][3]));
        }
        mxA = fmaxf(mxA, __shfl_xor_sync(0xffffffffu, mxA, 1));
        mxA = fmaxf(mxA, __shfl_xor_sync(0xffffffffu, mxA, 2));
        mxB = fmaxf(mxB, __shfl_xor_sync(0xffffffffu, mxB, 1));
        mxB = fmaxf(mxB, __shfl_xor_sync(0xffffffffu, mxB, 2));
        float mnA = fmaxf(mA, mxA), mnB = fmaxf(mB, mxB);
        float cA = __expf(mA - mnA), cB = __expf(mB - mnB);
        mA = mnA; mB = mnB;
        lA *= cA; lB *= cB;
#pragma unroll
        for (int nt = 0; nt < 16; nt++) {
            oacc[nt][0] *= cA; oacc[nt][1] *= cA;
            oacc[nt][2] *= cB; oacc[nt][3] *= cB;
        }
        float p[4][4];
#pragma unroll
        for (int nt = 0; nt < 4; nt++) {
            p[nt][0] = __expf(sacc[nt][0] - mnA);
            p[nt][1] = __expf(sacc[nt][1] - mnA);
            p[nt][2] = __expf(sacc[nt][2] - mnB);
            p[nt][3] = __expf(sacc[nt][3] - mnB);
            lA += p[nt][0] + p[nt][1];
            lB += p[nt][2] + p[nt][3];
        }

        // P fragments (hi/lo)
        uint32_t pha[2][4], pla[2][4];
#pragma unroll
        for (int pk = 0; pk < 2; pk++) {
            int n0t = 2 * pk, n1t = 2 * pk + 1;
            __nv_bfloat162 h0 = __floats2bfloat162_rn(p[n0t][0], p[n0t][1]);
            __nv_bfloat162 h1 = __floats2bfloat162_rn(p[n0t][2], p[n0t][3]);
            __nv_bfloat162 h2 = __floats2bfloat162_rn(p[n1t][0], p[n1t][1]);
            __nv_bfloat162 h3 = __floats2bfloat162_rn(p[n1t][2], p[n1t][3]);
            pha[pk][0] = *(uint32_t*)&h0; pha[pk][1] = *(uint32_t*)&h1;
            pha[pk][2] = *(uint32_t*)&h2; pha[pk][3] = *(uint32_t*)&h3;
            float2 f0 = __bfloat1622float2(h0), f1 = __bfloat1622float2(h1);
            float2 f2 = __bfloat1622float2(h2), f3 = __bfloat1622float2(h3);
            __nv_bfloat162 l0 = __floats2bfloat162_rn(p[n0t][0] - f0.x, p[n0t][1] - f0.y);
            __nv_bfloat162 l1 = __floats2bfloat162_rn(p[n0t][2] - f1.x, p[n0t][3] - f1.y);
            __nv_bfloat162 l2 = __floats2bfloat162_rn(p[n1t][0] - f2.x, p[n1t][1] - f2.y);
            __nv_bfloat162 l3 = __floats2bfloat162_rn(p[n1t][2] - f3.x, p[n1t][3] - f3.y);
            pla[pk][0] = *(uint32_t*)&l0; pla[pk][1] = *(uint32_t*)&l1;
            pla[pk][2] = *(uint32_t*)&l2; pla[pk][3] = *(uint32_t*)&l3;
        }

        // O += P @ V (bf16x3)
#pragma unroll
        for (int nt2 = 0; nt2 < 16; nt2++)
#pragma unroll
            for (int pk = 0; pk < 2; pk++) {
                const char* pb = as_ + AS_VH + (nt2 * 8 + gid) * 80 + (pk * 16 + tg * 2) * 2;
                uint32_t bh0 = *(const uint32_t*)pb;
                uint32_t bh1 = *(const uint32_t*)(pb + 16);
                const char* pbl = pb + (AS_VL - AS_VH);
                uint32_t bl0 = *(const uint32_t*)pbl;
                uint32_t bl1 = *(const uint32_t*)(pbl + 16);
                MMA_BF16(oacc[nt2], pha[pk], bh0, bh1);
                MMA_BF16(oacc[nt2], pha[pk], bl0, bl1);
                MMA_BF16(oacc[nt2], pla[pk], bh0, bh1);
            }
    }

    // finalize: 1/l, split to bf16 hi/lo, store
    lA += __shfl_xor_sync(0xffffffffu, lA, 1);
    lA += __shfl_xor_sync(0xffffffffu, lA, 2);
    lB += __shfl_xor_sync(0xffffffffu, lB, 1);
    lB += __shfl_xor_sync(0xffffffffu, lB, 2);
    float iA = 1.f / lA, iB = 1.f / lB;
#pragma unroll
    for (int nt2 = 0; nt2 < 16; nt2++) {
        int col = nt2 * 8 + tg * 2;
        size_t oA = ((size_t)rowA * HQ_ + hq) * HD_ + col;
        size_t oB = ((size_t)rowB * HQ_ + hq) * HD_ + col;
        float a0 = oacc[nt2][0] * iA, a1 = oacc[nt2][1] * iA;
        float b0 = oacc[nt2][2] * iB, b1 = oacc[nt2][3] * iB;
        __nv_bfloat162 ha = __floats2bfloat162_rn(a0, a1);
        float2 fa = __bfloat1622float2(ha);
        __nv_bfloat162 la = __floats2bfloat162_rn(a0 - fa.x, a1 - fa.y);
        __nv_bfloat162 hb = __floats2bfloat162_rn(b0, b1);
        float2 fb = __bfloat1622float2(hb);
        __nv_bfloat162 lb = __floats2bfloat162_rn(b0 - fb.x, b1 - fb.y);
        *(uint32_t*)(g_a1h + oA) = *(uint32_t*)&ha;
        *(uint32_t*)(g_a1l + oA) = *(uint32_t*)&la;
        *(uint32_t*)(g_a1h + oB) = *(uint32_t*)&hb;
        *(uint32_t*)(g_a1l + oB) = *(uint32_t*)&lb;
    }
}

// ---------------- residual add ----------------
__global__ void resadd_kernel(const float* __restrict__ hidden, float* __restrict__ outres) {
    for (int i = blockIdx.x * 256 + threadIdx.x; i < T_ * D_; i += gridDim.x * 256) {
        float r = g_attnproj[i] + hidden[i];
        g_res[i] = r;
        outres[i] = r;
    }
}

// ---------------- router top-k ----------------
__global__ void topk_kernel() {
    int t = blockIdx.x * 8 + (threadIdx.x >> 5);
    int lane = threadIdx.x & 31;
    const float* lg = g_logits + (size_t)t * E_;
    float v0 = lg[lane], v1 = lg[lane + 32];
    float mx = fmaxf(v0, v1);
#pragma unroll
    for (int o = 16; o; o >>= 1) mx = fmaxf(mx, __shfl_xor_sync(0xffffffffu, mx, o));
    float e0 = expf(v0 - mx), e1 = expf(v1 - mx);
    float ssum = e0 + e1;
#pragma unroll
    for (int o = 16; o; o >>= 1) ssum += __shfl_xor_sync(0xffffffffu, ssum, o);
    float p0 = e0 / ssum, p1 = e1 / ssum;
    float selv[TOPK_];
    int seli[TOPK_];
#pragma unroll
    for (int it = 0; it < TOPK_; it++) {
        float bv; int bi;
        if (p0 >= p1) { bv = p0; bi = lane; } else { bv = p1; bi = lane + 32; }
#pragma unroll
        for (int o = 16; o; o >>= 1) {
            float ov = __shfl_xor_sync(0xffffffffu, bv, o);
            int oi = __shfl_xor_sync(0xffffffffu, bi, o);
            if (ov > bv || (ov == bv && oi < bi)) { bv = ov; bi = oi; }
        }
        selv[it] = bv;
        seli[it] = bi;
        if (bi == lane) p0 = -1.f;
        if (bi == lane + 32) p1 = -1.f;
    }
    float tot = 0.f;
#pragma unroll
    for (int it = 0; it < TOPK_; it++) tot += selv[it];
    if (lane == 0) {
#pragma unroll
        for (int it = 0; it < TOPK_; it++) {
            g_topv[t * TOPK_ + it] = selv[it] / tot;
            g_topi[t * TOPK_ + it] = seli[it];
        }
    }
}

// ---------------- MoE routing bookkeeping ----------------
__global__ void zero_kernel() {
    int i = threadIdx.x;
    if (i < E_) { g_cnt[i] = 0; g_cur[i] = 0; }
}
__global__ void count_kernel() {
    int i = blockIdx.x * 256 + threadIdx.x;
    if (i < NTOK) atomicAdd(&g_cnt[g_topi[i]], 1);
}
__global__ void scan_kernel() {
    if (threadIdx.x == 0) {
        int a = 0;
        for (int e = 0; e < E_; e++) { g_off[e] = a; a += g_cnt[e]; }
        g_off[E_] = a;
    }
}
__global__ void assign_kernel() {
    int i = blockIdx.x * 256 + threadIdx.x;
    if (i < NTOK) {
        int e = g_topi[i];
        int r = g_off[e] + atomicAdd(&g_cur[e], 1);
        g_ptok[r] = i >> 3;
        g_rowof[i] = r;
    }
}

// ---------------- silu(gate) * up -> bf16 hi/lo ----------------
__global__ void silu_mul_kernel() {
    for (int i = blockIdx.x * 256 + threadIdx.x; i < NTOK * F_; i += gridDim.x * 256) {
        float g = g_gate[i];
        float u = g_up[i];
        float y = g / (1.f + __expf(-g)) * u;
        split2(y, g_a3h + i, g_a3l + i);
    }
}

// ---------------- combine expert outputs ----------------
__global__ void combine_kernel(float* __restrict__ out) {
    int t = blockIdx.x;
    float w[TOPK_];
    int rw[TOPK_];
#pragma unroll
    for (int j = 0; j < TOPK_; j++) {
        w[j] = g_topv[t * TOPK_ + j];
        rw[j] = g_rowof[t * TOPK_ + j];
    }
    for (int d = threadIdx.x; d < D_; d += 256) {
        float acc = 0.f;
#pragma unroll
        for (int j = 0; j < TOPK_; j++)
            acc += w[j] * g_ye[(size_t)rw[j] * D_ + d];
        out[(size_t)t * D_ + d] = acc;
    }
}

// ---------------- launch ----------------
extern "C" void kernel_launch(void* const* d_in, const int* in_sizes, int n_in,
                              void* d_out, int out_size) {
    const int* positions = (const int*)d_in[0];
    const float* hidden = (const float*)d_in[1];
    const float* in_ln = (const float*)d_in[2];
    const float* post_ln = (const float*)d_in[3];
    const float* qns = (const float*)d_in[4];
    const float* kns = (const float*)d_in[5];
    const float* wq = (const float*)d_in[6];
    const float* wk = (const float*)d_in[7];
    const float* wv = (const float*)d_in[8];
    const float* wo = (const float*)d_in[9];
    const float* wr = (const float*)d_in[10];
    const float* wg = (const float*)d_in[11];
    const float* wu = (const float*)d_in[12];
    const float* wd = (const float*)d_in[13];
    float* out = (float*)d_out;

    cudaFuncSetAttribute(mma_gemm, cudaFuncAttributeMaxDynamicSharedMemorySize, SM_TOTAL);
    cudaFuncSetAttribute(attn_kernel, cudaFuncAttributeMaxDynamicSharedMemorySize, AS_TOT);
    dim3 cb(32, 8);

    // weight convert + transpose (bf16 hi/lo, [N,K])
    convsplit_kernel<<<dim3(4096 / 32, 2048 / 32, 1), cb>>>(wq, 0, 2048, 4096);
    convsplit_kernel<<<dim3(512 / 32, 2048 / 32, 1), cb>>>(wk, 1, 2048, 512);
    convsplit_kernel<<<dim3(512 / 32, 2048 / 32, 1), cb>>>(wv, 2, 2048, 512);
    convsplit_kernel<<<dim3(2048 / 32, 4096 / 32, 1), cb>>>(wo, 3, 4096, 2048);
    convsplit_kernel<<<dim3(768 / 32, 2048 / 32, 64), cb>>>(wg, 4, 2048, 768);
    convsplit_kernel<<<dim3(768 / 32, 2048 / 32, 64), cb>>>(wu, 5, 2048, 768);
    convsplit_kernel<<<dim3(2048 / 32, 768 / 32, 64), cb>>>(wd, 6, 768, 2048);
    rope_table_kernel<<<T_, 64>>>(positions);

    // pre-attention norm + QKV projections (HMMA bf16x3)
    rmsnorm_kernel<<<T_, 256>>>(hidden, 0, 0, in_ln);
    mma_gemm<<<dim3(32, 16, 1), 256, SM_TOTAL>>>(0, 0, 1, 0, 0, D_, HQ_ * HD_, 0);
    mma_gemm<<<dim3(4, 16, 1), 256, SM_TOTAL>>>(0, 1, 2, 0, 0, D_, HKV_ * HD_, 0);
    mma_gemm<<<dim3(4, 16, 1), 256, SM_TOTAL>>>(0, 2, 3, 0, 0, D_, HKV_ * HD_, 0);
    // per-head rmsnorm + rope
    qknorm_rope_kernel<<<dim3(T_, HQ_), HD_>>>(1, qns, HQ_);
    qknorm_rope_kernel<<<dim3(T_, HKV_), HD_>>>(2, kns, HKV_);
    // causal attention (HMMA) + output projection + residual
    attn_kernel<<<dim3(T_ / 64, HQ_), 128, AS_TOT>>>();
    mma_gemm<<<dim3(16, 16, 1), 256, SM_TOTAL>>>(1, 3, 5, 0, 0, HQ_ * HD_, D_, 0);
    resadd_kernel<<<2048, 256>>>(hidden, out + (size_t)T_ * D_);
    // post-attention norm + router (exact fp32) + top-k
    rmsnorm_kernel<<<T_, 256>>>(nullptr, 6, 2, post_ln);
    gemm_kernel<<<dim3(1, 16, 1), 256>>>(6, wr, 7, 0, 0, D_, E_, 0);
    topk_kernel<<<T_ / 8, 256>>>();
    // expert grouping
    zero_kernel<<<1, 64>>>();
    count_kernel<<<NTOK / 256, 256>>>();
    scan_kernel<<<1, 32>>>();
    assign_kernel<<<NTOK / 256, 256>>>();
    // expert GEMMs (HMMA, grouped, gathered)
    mma_gemm<<<dim3(6, 24, 64), 256, SM_TOTAL>>>(2, 4, 8, 1, 1, D_, F_, (long)F_ * D_);
    mma_gemm<<<dim3(6, 24, 64), 256, SM_TOTAL>>>(2, 5, 9, 1, 1, D_, F_, (long)F_ * D_);
    silu_mul_kernel<<<8192, 256>>>();
    mma_gemm<<<dim3(16, 24, 64), 256, SM_TOTAL>>>(3, 6, 10, 1, 0, F_, D_, (long)D_ * F_);
    combine_kernel<<<T_, 256>>>(out);
}

// round 11
// speedup vs baseline: 4.6124x; 1.0591x over previous
#include <cuda_runtime.h>
#include <cuda_bf16.h>
#include <math.h>
#include <stdint.h>

#define T_    2048
#define D_    2048
#define HQ_   32
#define HKV_  4
#define HD_   128
#define E_    64
#define TOPK_ 8
#define F_    768
#define NTOK  (T_ * TOPK_)

// ---------------- scratch (static device globals; no allocation) ----------------
__device__ float g_hnorm[T_ * D_];
__device__ float g_q[T_ * HQ_ * HD_];
__device__ float g_k[T_ * HKV_ * HD_];
__device__ float g_v[T_ * HKV_ * HD_];
__device__ float g_attn[T_ * HQ_ * HD_];   // unused (kept for buf ids)
__device__ float g_attnproj[T_ * D_];
__device__ float g_res[T_ * D_];
__device__ float g_h2[T_ * D_];
__device__ float g_logits[T_ * E_];
__device__ float g_topv[NTOK];
__device__ int   g_topi[NTOK];
__device__ int   g_cnt[E_];
__device__ int   g_cur[E_];
__device__ int   g_off[E_ + 1];
__device__ int   g_ptok[NTOK];
__device__ int   g_rowof[NTOK];
__device__ float g_gate[NTOK * F_];
__device__ float g_up[NTOK * F_];
__device__ float g_ye[(size_t)NTOK * D_];
__device__ int   g_segT[2] = {0, T_};
__device__ float g_rcos[T_ * 64];
__device__ float g_rsin[T_ * 64];

// activation hi/lo bf16 buffers
__device__ __align__(16) __nv_bfloat16 g_a0h[T_ * D_];            // hnorm
__device__ __align__(16) __nv_bfloat16 g_a0l[T_ * D_];
__device__ __align__(16) __nv_bfloat16 g_a1h[T_ * HQ_ * HD_];     // attn out
__device__ __align__(16) __nv_bfloat16 g_a1l[T_ * HQ_ * HD_];
__device__ __align__(16) __nv_bfloat16 g_a2h[T_ * D_];            // h2
__device__ __align__(16) __nv_bfloat16 g_a2l[T_ * D_];
__device__ __align__(16) __nv_bfloat16 g_a3h[(size_t)NTOK * F_];  // silu*up
__device__ __align__(16) __nv_bfloat16 g_a3l[(size_t)NTOK * F_];

// transposed bf16 hi/lo weight copies ([N,K] K-major per expert)
__device__ __align__(16) __nv_bfloat16 g_wq_h[(size_t)4096 * 2048];
__device__ __align__(16) __nv_bfloat16 g_wq_l[(size_t)4096 * 2048];
__device__ __align__(16) __nv_bfloat16 g_wk_h[(size_t)512 * 2048];
__device__ __align__(16) __nv_bfloat16 g_wk_l[(size_t)512 * 2048];
__device__ __align__(16) __nv_bfloat16 g_wv_h[(size_t)512 * 2048];
__device__ __align__(16) __nv_bfloat16 g_wv_l[(size_t)512 * 2048];
__device__ __align__(16) __nv_bfloat16 g_wo_h[(size_t)2048 * 4096];
__device__ __align__(16) __nv_bfloat16 g_wo_l[(size_t)2048 * 4096];
__device__ __align__(16) __nv_bfloat16 g_wg_h[(size_t)E_ * F_ * D_];
__device__ __align__(16) __nv_bfloat16 g_wg_l[(size_t)E_ * F_ * D_];
__device__ __align__(16) __nv_bfloat16 g_wu_h[(size_t)E_ * F_ * D_];
__device__ __align__(16) __nv_bfloat16 g_wu_l[(size_t)E_ * F_ * D_];
__device__ __align__(16) __nv_bfloat16 g_wd_h[(size_t)E_ * D_ * F_];
__device__ __align__(16) __nv_bfloat16 g_wd_l[(size_t)E_ * D_ * F_];

__device__ __forceinline__ float* buf_ptr(int id) {
    switch (id) {
        case 0: return g_hnorm;
        case 1: return g_q;
        case 2: return g_k;
        case 3: return g_v;
        case 4: return g_attn;
        case 5: return g_attnproj;
        case 6: return g_h2;
        case 7: return g_logits;
        case 8: return g_gate;
        case 9: return g_up;
        default: return g_ye;
    }
}
__device__ __forceinline__ __nv_bfloat16* bsel(int id, int hi) {
    switch (id) {
        case 0: return hi ? g_wq_h : g_wq_l;
        case 1: return hi ? g_wk_h : g_wk_l;
        case 2: return hi ? g_wv_h : g_wv_l;
        case 3: return hi ? g_wo_h : g_wo_l;
        case 4: return hi ? g_wg_h : g_wg_l;
        case 5: return hi ? g_wu_h : g_wu_l;
        default: return hi ? g_wd_h : g_wd_l;
    }
}
__device__ __forceinline__ __nv_bfloat16* asel(int id, int hi) {
    switch (id) {
        case 0: return hi ? g_a0h : g_a0l;
        case 1: return hi ? g_a1h : g_a1l;
        case 2: return hi ? g_a2h : g_a2l;
        default: return hi ? g_a3h : g_a3l;
    }
}
__device__ __forceinline__ void split2(float v, __nv_bfloat16* h, __nv_bfloat16* l) {
    __nv_bfloat16 hh = __float2bfloat16(v);
    *h = hh;
    *l = __float2bfloat16(v - __bfloat162float(hh));
}

__device__ __forceinline__ uint32_t smem_u32(const void* p) {
    uint32_t a;
    asm("{ .reg .u64 t; cvta.to.shared.u64 t, %1; cvt.u32.u64 %0, t; }" : "=r"(a) : "l"(p));
    return a;
}
#define CP16(d, s) asm volatile("cp.async.cg.shared.global [%0], [%1], 16;" :: "r"(d), "l"(s) : "memory")
#define MMA_BF16(c, a, b0, b1) \
    asm volatile("mma.sync.aligned.m16n8k16.row.col.f32.bf16.bf16.f32 " \
        "{%0,%1,%2,%3}, {%4,%5,%6,%7}, {%8,%9}, {%0,%1,%2,%3};" \
        : "+f"((c)[0]), "+f"((c)[1]), "+f"((c)[2]), "+f"((c)[3]) \
        : "r"((a)[0]), "r"((a)[1]), "r"((a)[2]), "r"((a)[3]), "r"(b0), "r"(b1))
#define LDSM4(r, a) \
    asm volatile("ldmatrix.sync.aligned.m8n8.x4.shared.b16 {%0,%1,%2,%3}, [%4];" \
        : "=r"((r)[0]), "=r"((r)[1]), "=r"((r)[2]), "=r"((r)[3]) : "r"(a))

// SMEM for mma_gemm: 2 stages x 4 matrices x 128 rows x 80B
#define MATB 10240
#define STGB 40960
#define SM_TOTAL 81920

// ---------------- convert + transpose: fp32 [K,N] -> bf16 hi/lo [N,K] ----------------
// tile: 64 k x 32 n; writes 128B-contiguous per warp
__global__ void convsplit_kernel(const float* __restrict__ W, int oid, int K, int N) {
    __shared__ float t[32][65];
    long base = (long)blockIdx.z * (long)K * N;
    int kb = blockIdx.y * 64, nb = blockIdx.x * 32;
    int tx = threadIdx.x, ty = threadIdx.y;  // 32 x 8
    __nv_bfloat16* Oh = bsel(oid, 1);
    __nv_bfloat16* Ol = bsel(oid, 0);
#pragma unroll
    for (int j = 0; j < 8; j++) {
        int k = ty + j * 8;
        t[tx][k] = W[base + (long)(kb + k) * N + nb + tx];
    }
    __syncthreads();
    int id = ty * 32 + tx;
#pragma unroll
    for (int j = 0; j < 4; j++) {
        int item = id + j * 256;       // 0..1023
        int row = item >> 5;           // n 0..31
        int cp = item & 31;            // k-pair 0..31
        float v0 = t[row][2 * cp], v1 = t[row][2 * cp + 1];
        __nv_bfloat162 h = __floats2bfloat162_rn(v0, v1);
        float2 hf = __bfloat1622float2(h);
        __nv_bfloat162 l = __floats2bfloat162_rn(v0 - hf.x, v1 - hf.y);
        long o = base + (long)(nb + row) * K + kb + 2 * cp;
        *(uint32_t*)(Oh + o) = *(uint32_t*)&h;
        *(uint32_t*)(Ol + o) = *(uint32_t*)&l;
    }
}

// ---------------- HMMA bf16x3 GEMM (ldmatrix staging) ----------------
__global__ void __launch_bounds__(256, 2) mma_gemm(
    int aid, int bid, int cid, int segid, int usemap, int K, int Ntot, long wstride) {
    extern __shared__ char sm[];
    const int* seg = segid ? g_off : g_segT;
    int e = blockIdx.z;
    int segs = seg[e], sege = seg[e + 1];
    int m0 = segs + blockIdx.y * 128;
    if (m0 >= sege) return;
    int n0 = blockIdx.x * 128;
    const __nv_bfloat16* Ah = asel(aid, 1);
    const __nv_bfloat16* Al = asel(aid, 0);
    const __nv_bfloat16* Bh = bsel(bid, 1) + (long)e * wstride;
    const __nv_bfloat16* Bl = bsel(bid, 0) + (long)e * wstride;
    float* C = buf_ptr(cid);

    int tid = threadIdx.x;
    int lane = tid & 31, wid = tid >> 5;
    int gid = lane >> 2, tg = lane & 3;
    int m_off = (wid & 3) * 32, n_off = (wid >> 2) * 64;

    int r = tid >> 2, c16 = tid & 3;
    int gr0 = m0 + r;      if (gr0 > sege - 1) gr0 = sege - 1;
    int gr1 = m0 + r + 64; if (gr1 > sege - 1) gr1 = sege - 1;
    long a0off = (long)(usemap ? g_ptok[gr0] : gr0) * K + c16 * 8;
    long a1off = (long)(usemap ? g_ptok[gr1] : gr1) * K + c16 * 8;
    long b0off = (long)(n0 + r) * K + c16 * 8;
    long b1off = (long)(n0 + r + 64) * K + c16 * 8;
    uint32_t sb = smem_u32(sm);
    uint32_t d0 = sb + (uint32_t)(r * 80 + c16 * 16);
    uint32_t d1 = sb + (uint32_t)((r + 64) * 80 + c16 * 16);

    // ldmatrix lane-address components
    uint32_t a_lrow = (uint32_t)(m_off + (lane & 15)) * 80 + ((uint32_t)(lane >> 4)) * 16;
    uint32_t b_lrow = (uint32_t)(n_off + ((lane >> 4) << 3) + (lane & 7)) * 80 + (((uint32_t)(lane >> 3) & 1)) * 16;

    float acc[2][8][4];
#pragma unroll
    for (int mt = 0; mt < 2; mt++)
#pragma unroll
        for (int nt = 0; nt < 8; nt++)
#pragma unroll
            for (int j = 0; j < 4; j++) acc[mt][nt][j] = 0.f;

    auto prefetch = [&](int buf, int k0) {
        uint32_t s = (uint32_t)buf * STGB;
        CP16(d0 + s, Ah + a0off + k0);
        CP16(d1 + s, Ah + a1off + k0);
        CP16(d0 + s + MATB, Al + a0off + k0);
        CP16(d1 + s + MATB, Al + a1off + k0);
        CP16(d0 + s + 2 * MATB, Bh + b0off + k0);
        CP16(d1 + s + 2 * MATB, Bh + b1off + k0);
        CP16(d0 + s + 3 * MATB, Bl + b0off + k0);
        CP16(d1 + s + 3 * MATB, Bl + b1off + k0);
        asm volatile("cp.async.commit_group;" ::: "memory");
    };

    int nk = K / 32;
    prefetch(0, 0);
    for (int kc = 0; kc < nk; kc++) {
        if (kc + 1 < nk) {
            prefetch((kc + 1) & 1, (kc + 1) * 32);
            asm volatile("cp.async.wait_group 1;" ::: "memory");
        } else {
            asm volatile("cp.async.wait_group 0;" ::: "memory");
        }
        __syncthreads();
        uint32_t stg = sb + (uint32_t)(kc & 1) * STGB;
#pragma unroll
        for (int ks = 0; ks < 2; ks++) {
            uint32_t kbyte = (uint32_t)ks * 32;
            uint32_t a_h[2][4], a_l[2][4];
#pragma unroll
            for (int mt = 0; mt < 2; mt++) {
                uint32_t aaddr = stg + a_lrow + (uint32_t)mt * (16 * 80) + kbyte;
                LDSM4(a_h[mt], aaddr);
                LDSM4(a_l[mt], aaddr + MATB);
            }
#pragma unroll
            for (int n2 = 0; n2 < 4; n2++) {
                uint32_t bh[4], bl[4];
                uint32_t baddr = stg + 2 * MATB + b_lrow + (uint32_t)n2 * (16 * 80) + kbyte;
                LDSM4(bh, baddr);
                LDSM4(bl, baddr + MATB);
#pragma unroll
                for (int nt2 = 0; nt2 < 2; nt2++) {
                    int nt = n2 * 2 + nt2;
#pragma unroll
                    for (int mt = 0; mt < 2; mt++) {
                        MMA_BF16(acc[mt][nt], a_h[mt], bh[nt2 * 2], bh[nt2 * 2 + 1]);
                        MMA_BF16(acc[mt][nt], a_h[mt], bl[nt2 * 2], bl[nt2 * 2 + 1]);
                        MMA_BF16(acc[mt][nt], a_l[mt], bh[nt2 * 2], bh[nt2 * 2 + 1]);
                    }
                }
            }
        }
        __syncthreads();
    }

#pragma unroll
    for (int mt = 0; mt < 2; mt++) {
        int row = m0 + m_off + mt * 16 + gid;
#pragma unroll
        for (int nt = 0; nt < 8; nt++) {
            int col = n0 + n_off + nt * 8 + tg * 2;
            if (row < sege)
                *(float2*)(C + (long)row * Ntot + col) = make_float2(acc[mt][nt][0], acc[mt][nt][1]);
            if (row + 8 < sege)
                *(float2*)(C + (long)(row + 8) * Ntot + col) = make_float2(acc[mt][nt][2], acc[mt][nt][3]);
        }
    }
}

// ---------------- rmsnorm over D=2048: fp32 out + bf16 hi/lo pair ----------------
__global__ void rmsnorm_kernel(const float* __restrict__ xext, int oid, int pairid,
                               const float* __restrict__ scale) {
    const float* x = xext ? xext : g_res;
    float* out = buf_ptr(oid);
    __nv_bfloat16* ph = asel(pairid, 1);
    __nv_bfloat16* pl = asel(pairid, 0);
    int t = blockIdx.x;
    int tid = threadIdx.x;
    const float* xr = x + (size_t)t * D_;
    float v[8];
    float ss = 0.f;
#pragma unroll
    for (int j = 0; j < 8; j++) { v[j] = xr[tid + j * 256]; ss += v[j] * v[j]; }
#pragma unroll
    for (int o = 16; o; o >>= 1) ss += __shfl_xor_sync(0xffffffffu, ss, o);
    __shared__ float ws[8];
    if ((tid & 31) == 0) ws[tid >> 5] = ss;
    __syncthreads();
    float tot = 0.f;
#pragma unroll
    for (int w = 0; w < 8; w++) tot += ws[w];
    float inv = rsqrtf(tot / (float)D_ + 1e-6f);
    size_t rb = (size_t)t * D_;
#pragma unroll
    for (int j = 0; j < 8; j++) {
        int c = tid + j * 256;
        float y = v[j] * inv * scale[c];
        out[rb + c] = y;
        split2(y, ph + rb + c, pl + rb + c);
    }
}

// ---------------- fp32 SIMT GEMM (router only) ----------------
__global__ void __launch_bounds__(256) gemm_kernel(
    int xid, const float* __restrict__ W, int cid,
    int segid, int usemap, int K, int N, long wstride) {
    const int* seg = segid ? g_off : g_segT;
    int e = blockIdx.z;
    int segs = seg[e], sege = seg[e + 1];
    int m0 = segs + blockIdx.y * 128;
    if (m0 >= sege) return;
    const float* X = buf_ptr(xid);
    float* C = buf_ptr(cid);
    const float* Wp = W + (long)e * wstride;
    int n0 = blockIdx.x * 128;

    __shared__ float As[8][132];
    __shared__ float Bs[8][128];

    int tid = threadIdx.x;
    int am = tid >> 1, ak = (tid & 1) * 4;
    int bk = tid >> 5, bn = (tid & 31) * 4;
    int tx = tid & 15, ty = tid >> 4;

    int gr = m0 + am;
    bool avalid = gr < sege;
    int arow = avalid ? (usemap ? g_ptok[gr] : gr) : 0;
    const float* ap = X + (long)arow * K + ak;
    const float* bp = Wp + (long)bk * N + n0 + bn;
    bool bvalid = (n0 + bn) < N;

    float acc[8][8];
#pragma unroll
    for (int i = 0; i < 8; i++)
#pragma unroll
        for (int j = 0; j < 8; j++) acc[i][j] = 0.f;

    for (int k0 = 0; k0 < K; k0 += 8) {
        float4 a4 = avalid ? *(const float4*)(ap + k0) : make_float4(0, 0, 0, 0);
        float4 b4 = bvalid ? *(const float4*)(bp + (long)k0 * N) : make_float4(0, 0, 0, 0);
        __syncthreads();
        As[ak + 0][am] = a4.x;
        As[ak + 1][am] = a4.y;
        As[ak + 2][am] = a4.z;
        As[ak + 3][am] = a4.w;
        *(float4*)&Bs[bk][bn] = b4;
        __syncthreads();
#pragma unroll
        for (int kk = 0; kk < 8; kk++) {
            float ar[8], br[8];
            *(float4*)&ar[0] = *(const float4*)&As[kk][ty * 8];
            *(float4*)&ar[4] = *(const float4*)&As[kk][ty * 8 + 4];
            *(float4*)&br[0] = *(const float4*)&Bs[kk][tx * 8];
            *(float4*)&br[4] = *(const float4*)&Bs[kk][tx * 8 + 4];
#pragma unroll
            for (int i = 0; i < 8; i++)
#pragma unroll
                for (int j = 0; j < 8; j++) acc[i][j] += ar[i] * br[j];
        }
    }
    bool cn = (n0 + tx * 8) < N;
#pragma unroll
    for (int i = 0; i < 8; i++) {
        int row = m0 + ty * 8 + i;
        if (row < sege && cn) {
            float* cp = C + (long)row * N + n0 + tx * 8;
            *(float4*)cp = make_float4(acc[i][0], acc[i][1], acc[i][2], acc[i][3]);
            *(float4*)(cp + 4) = make_float4(acc[i][4], acc[i][5], acc[i][6], acc[i][7]);
        }
    }
}

// ---------------- rope table (double precision, once) ----------------
__global__ void rope_table_kernel(const int* __restrict__ positions) {
    int t = blockIdx.x, d = threadIdx.x;
    double invf = exp(-13.815510557964274 * ((double)d / 64.0));
    double ang = (double)positions[t] * invf;
    g_rcos[t * 64 + d] = (float)cos(ang);
    g_rsin[t * 64 + d] = (float)sin(ang);
}

// ---------------- per-head rmsnorm (HD=128) + RoPE, in place ----------------
__global__ void qknorm_rope_kernel(int bid, const float* __restrict__ sc, int H) {
    float* buf = buf_ptr(bid);
    int t = blockIdx.x, h = blockIdx.y;
    float* x = buf + ((size_t)t * H + h) * HD_;
    int d = threadIdx.x;
    float v = x[d];
    float sq = v * v;
#pragma unroll
    for (int o = 16; o; o >>= 1) sq += __shfl_xor_sync(0xffffffffu, sq, o);
    __shared__ float ws[4];
    __shared__ float sh[HD_];
    if ((d & 31) == 0) ws[d >> 5] = sq;
    __syncthreads();
    float tot = ws[0] + ws[1] + ws[2] + ws[3];
    float xn = v * rsqrtf(tot / 128.f + 1e-6f) * sc[d];
    sh[d] = xn;
    __syncthreads();
    if (d < 64) {
        float c = g_rcos[t * 64 + d];
        float s = g_rsin[t * 64 + d];
        float x1 = sh[d], x2 = sh[d + 64];
        x[d] = x1 * c - x2 * s;
        x[d + 64] = x2 * c + x1 * s;
    }
}

// ---------------- HMMA causal flash attention ----------------
// grid (T/64, HQ), block 128 (4 warps x 16 q-rows). k-tile = 32 cols.
#define AS_QH 0
#define AS_QL 17408
#define AS_KH 34816
#define AS_KL 43520
#define AS_VH 52224
#define AS_VL 62464
#define AS_TOT 72704

__global__ void __launch_bounds__(128) attn_kernel() {
    extern __shared__ char as_[];
    int hq = blockIdx.y, kvh = hq >> 3;
    int q0 = blockIdx.x * 64;
    int tid = threadIdx.x, lane = tid & 31, wid = tid >> 5;
    int gid = lane >> 2, tg = lane & 3;
    int m0w = wid * 16;
    const float qscale = 0.08838834764831845f;

    // stage Q (scaled, split hi/lo, padded rows of 272B)
    for (int idx = tid; idx < 64 * 32; idx += 128) {
        int r = idx >> 5, d = (idx & 31) * 4;
        float4 v = *(const float4*)(g_q + ((size_t)(q0 + r) * HQ_ + hq) * HD_ + d);
        v.x *= qscale; v.y *= qscale; v.z *= qscale; v.w *= qscale;
        __nv_bfloat162 h01 = __floats2bfloat162_rn(v.x, v.y);
        __nv_bfloat162 h23 = __floats2bfloat162_rn(v.z, v.w);
        float2 f01 = __bfloat1622float2(h01), f23 = __bfloat1622float2(h23);
        __nv_bfloat162 l01 = __floats2bfloat162_rn(v.x - f01.x, v.y - f01.y);
        __nv_bfloat162 l23 = __floats2bfloat162_rn(v.z - f23.x, v.w - f23.y);
        *(uint2*)(as_ + AS_QH + r * 272 + d * 2) = make_uint2(*(uint32_t*)&h01, *(uint32_t*)&h23);
        *(uint2*)(as_ + AS_QL + r * 272 + d * 2) = make_uint2(*(uint32_t*)&l01, *(uint32_t*)&l23);
    }
    __syncthreads();

    // Q fragments in registers (8 ksteps)
    uint32_t qh[8][4], ql[8][4];
#pragma unroll
    for (int ks = 0; ks < 8; ks++) {
        const char* pa = as_ + AS_QH + (m0w + gid) * 272 + (ks * 16 + tg * 2) * 2;
        qh[ks][0] = *(const uint32_t*)pa;
        qh[ks][1] = *(const uint32_t*)(pa + 8 * 272);
        qh[ks][2] = *(const uint32_t*)(pa + 16);
        qh[ks][3] = *(const uint32_t*)(pa + 8 * 272 + 16);
        const char* pl = pa + (AS_QL - AS_QH);
        ql[ks][0] = *(const uint32_t*)pl;
        ql[ks][1] = *(const uint32_t*)(pl + 8 * 272);
        ql[ks][2] = *(const uint32_t*)(pl + 16);
        ql[ks][3] = *(const uint32_t*)(pl + 8 * 272 + 16);
    }

    float oacc[16][4];
#pragma unroll
    for (int nt = 0; nt < 16; nt++)
#pragma unroll
        for (int j = 0; j < 4; j++) oacc[nt][j] = 0.f;
    float mA = -INFINITY, mB = -INFINITY, lA = 0.f, lB = 0.f;
    int rowA = q0 + m0w + gid, rowB = rowA + 8;

    int nkt = q0 / 32 + 2;
    for (int kt = 0; kt < nkt; kt++) {
        int c0 = kt * 32;
        __syncthreads();
        // stage K tile [32 kcols][128] hi/lo
        {
            int r = tid >> 2;
#pragma unroll
            for (int cc = 0; cc < 8; cc++) {
                int d = ((tid & 3) + cc * 4) * 4;
                float4 v = *(const float4*)(g_k + ((size_t)(c0 + r) * HKV_ + kvh) * HD_ + d);
                __nv_bfloat162 h01 = __floats2bfloat162_rn(v.x, v.y);
                __nv_bfloat162 h23 = __floats2bfloat162_rn(v.z, v.w);
                float2 f01 = __bfloat1622float2(h01), f23 = __bfloat1622float2(h23);
                __nv_bfloat162 l01 = __floats2bfloat162_rn(v.x - f01.x, v.y - f01.y);
                __nv_bfloat162 l23 = __floats2bfloat162_rn(v.z - f23.x, v.w - f23.y);
                *(uint2*)(as_ + AS_KH + r * 272 + d * 2) = make_uint2(*(uint32_t*)&h01, *(uint32_t*)&h23);
                *(uint2*)(as_ + AS_KL + r * 272 + d * 2) = make_uint2(*(uint32_t*)&l01, *(uint32_t*)&l23);
            }
        }
        // stage V transposed [128 d][32 kcols] hi/lo (rows padded to 80B)
        {
#pragma unroll
            for (int j = 0; j < 16; j++) {
                float v0 = g_v[((size_t)(c0 + 2 * j) * HKV_ + kvh) * HD_ + tid];
                float v1 = g_v[((size_t)(c0 + 2 * j + 1) * HKV_ + kvh) * HD_ + tid];
                __nv_bfloat162 h = __floats2bfloat162_rn(v0, v1);
                float2 hf = __bfloat1622float2(h);
                __nv_bfloat162 l = __floats2bfloat162_rn(v0 - hf.x, v1 - hf.y);
                *(uint32_t*)(as_ + AS_VH + tid * 80 + j * 4) = *(uint32_t*)&h;
                *(uint32_t*)(as_ + AS_VL + tid * 80 + j * 4) = *(uint32_t*)&l;
            }
        }
        __syncthreads();

        // S = Q @ K^T (bf16x3)
        float sacc[4][4];
#pragma unroll
        for (int nt = 0; nt < 4; nt++)
#pragma unroll
            for (int j = 0; j < 4; j++) sacc[nt][j] = 0.f;
#pragma unroll
        for (int ks = 0; ks < 8; ks++)
#pragma unroll
            for (int nt = 0; nt < 4; nt++) {
                const char* pb = as_ + AS_KH + (nt * 8 + gid) * 272 + (ks * 16 + tg * 2) * 2;
                uint32_t bh0 = *(const uint32_t*)pb;
                uint32_t bh1 = *(const uint32_t*)(pb + 16);
                const char* pbl = pb + (AS_KL - AS_KH);
                uint32_t bl0 = *(const uint32_t*)pbl;
                uint32_t bl1 = *(const uint32_t*)(pbl + 16);
                MMA_BF16(sacc[nt], qh[ks], bh0, bh1);
                MMA_BF16(sacc[nt], qh[ks], bl0, bl1);
                MMA_BF16(sacc[nt], ql[ks], bh0, bh1);
            }

        // causal mask
        if (c0 + 31 > rowA) {
#pragma unroll
            for (int nt = 0; nt < 4; nt++) {
                int cb = c0 + nt * 8 + tg * 2;
                if (cb > rowA) sacc[nt][0] = -1e30f;
                if (cb + 1 > rowA) sacc[nt][1] = -1e30f;
            }
        }
        if (c0 + 31 > rowB) {
#pragma unroll
            for (int nt = 0; nt < 4; nt++) {
                int cb = c0 + nt * 8 + tg * 2;
                if (cb > rowB) sacc[nt][2] = -1e30f;
                if (cb + 1 > rowB) sacc[nt][3] = -1e30f;
            }
        }

        // online softmax
        float mxA = -INFINITY, mxB = -INFINITY;
#pragma unroll
        for (int nt = 0; nt < 4; nt++) {
            mxA = fmaxf(mxA, fmaxf(sacc[nt][0], sacc[nt][1]));
            mxB = fmaxf(mxB, fmaxf(sacc[nt][2], sacc[nt][3]));
        }
        mxA = fmaxf(mxA, __shfl_xor_sync(0xffffffffu, mxA, 1));
        mxA = fmaxf(mxA, __shfl_xor_sync(0xffffffffu, mxA, 2));
        mxB = fmaxf(mxB, __shfl_xor_sync(0xffffffffu, mxB, 1));
        mxB = fmaxf(mxB, __shfl_xor_sync(0xffffffffu, mxB, 2));
        float mnA = fmaxf(mA, mxA), mnB = fmaxf(mB, mxB);
        float cA = __expf(mA - mnA), cB = __expf(mB - mnB);
        mA = mnA; mB = mnB;
        lA *= cA; lB *= cB;
#pragma unroll
        for (int nt = 0; nt < 16; nt++) {
            oacc[nt][0] *= cA; oacc[nt][1] *= cA;
            oacc[nt][2] *= cB; oacc[nt][3] *= cB;
        }
        float p[4][4];
#pragma unroll
        for (int nt = 0; nt < 4; nt++) {
            p[nt][0] = __expf(sacc[nt][0] - mnA);
            p[nt][1] = __expf(sacc[nt][1] - mnA);
            p[nt][2] = __expf(sacc[nt][2] - mnB);
            p[nt][3] = __expf(sacc[nt][3] - mnB);
            lA += p[nt][0] + p[nt][1];
            lB += p[nt][2] + p[nt][3];
        }

        // P fragments (hi/lo)
        uint32_t pha[2][4], pla[2][4];
#pragma unroll
        for (int pk = 0; pk < 2; pk++) {
            int n0t = 2 * pk, n1t = 2 * pk + 1;
            __nv_bfloat162 h0 = __floats2bfloat162_rn(p[n0t][0], p[n0t][1]);
            __nv_bfloat162 h1 = __floats2bfloat162_rn(p[n0t][2], p[n0t][3]);
            __nv_bfloat162 h2 = __floats2bfloat162_rn(p[n1t][0], p[n1t][1]);
            __nv_bfloat162 h3 = __floats2bfloat162_rn(p[n1t][2], p[n1t][3]);
            pha[pk][0] = *(uint32_t*)&h0; pha[pk][1] = *(uint32_t*)&h1;
            pha[pk][2] = *(uint32_t*)&h2; pha[pk][3] = *(uint32_t*)&h3;
            float2 f0 = __bfloat1622float2(h0), f1 = __bfloat1622float2(h1);
            float2 f2 = __bfloat1622float2(h2), f3 = __bfloat1622float2(h3);
            __nv_bfloat162 l0 = __floats2bfloat162_rn(p[n0t][0] - f0.x, p[n0t][1] - f0.y);
            __nv_bfloat162 l1 = __floats2bfloat162_rn(p[n0t][2] - f1.x, p[n0t][3] - f1.y);
            __nv_bfloat162 l2 = __floats2bfloat162_rn(p[n1t][0] - f2.x, p[n1t][1] - f2.y);
            __nv_bfloat162 l3 = __floats2bfloat162_rn(p[n1t][2] - f3.x, p[n1t][3] - f3.y);
            pla[pk][0] = *(uint32_t*)&l0; pla[pk][1] = *(uint32_t*)&l1;
            pla[pk][2] = *(uint32_t*)&l2; pla[pk][3] = *(uint32_t*)&l3;
        }

        // O += P @ V (bf16x3)
#pragma unroll
        for (int nt2 = 0; nt2 < 16; nt2++)
#pragma unroll
            for (int pk = 0; pk < 2; pk++) {
                const char* pb = as_ + AS_VH + (nt2 * 8 + gid) * 80 + (pk * 16 + tg * 2) * 2;
                uint32_t bh0 = *(const uint32_t*)pb;
                uint32_t bh1 = *(const uint32_t*)(pb + 16);
                const char* pbl = pb + (AS_VL - AS_VH);
                uint32_t bl0 = *(const uint32_t*)pbl;
                uint32_t bl1 = *(const uint32_t*)(pbl + 16);
                MMA_BF16(oacc[nt2], pha[pk], bh0, bh1);
                MMA_BF16(oacc[nt2], pha[pk], bl0, bl1);
                MMA_BF16(oacc[nt2], pla[pk], bh0, bh1);
            }
    }

    // finalize: 1/l, split to bf16 hi/lo, store
    lA += __shfl_xor_sync(0xffffffffu, lA, 1);
    lA += __shfl_xor_sync(0xffffffffu, lA, 2);
    lB += __shfl_xor_sync(0xffffffffu, lB, 1);
    lB += __shfl_xor_sync(0xffffffffu, lB, 2);
    float iA = 1.f / lA, iB = 1.f / lB;
#pragma unroll
    for (int nt2 = 0; nt2 < 16; nt2++) {
        int col = nt2 * 8 + tg * 2;
        size_t oA = ((size_t)rowA * HQ_ + hq) * HD_ + col;
        size_t oB = ((size_t)rowB * HQ_ + hq) * HD_ + col;
        float a0 = oacc[nt2][0] * iA, a1 = oacc[nt2][1] * iA;
        float b0 = oacc[nt2][2] * iB, b1 = oacc[nt2][3] * iB;
        __nv_bfloat162 ha = __floats2bfloat162_rn(a0, a1);
        float2 fa = __bfloat1622float2(ha);
        __nv_bfloat162 la = __floats2bfloat162_rn(a0 - fa.x, a1 - fa.y);
        __nv_bfloat162 hb = __floats2bfloat162_rn(b0, b1);
        float2 fb = __bfloat1622float2(hb);
        __nv_bfloat162 lb = __floats2bfloat162_rn(b0 - fb.x, b1 - fb.y);
        *(uint32_t*)(g_a1h + oA) = *(uint32_t*)&ha;
        *(uint32_t*)(g_a1l + oA) = *(uint32_t*)&la;
        *(uint32_t*)(g_a1h + oB) = *(uint32_t*)&hb;
        *(uint32_t*)(g_a1l + oB) = *(uint32_t*)&lb;
    }
}

// ---------------- residual add ----------------
__global__ void resadd_kernel(const float* __restrict__ hidden, float* __restrict__ outres) {
    for (int i = blockIdx.x * 256 + threadIdx.x; i < T_ * D_; i += gridDim.x * 256) {
        float r = g_attnproj[i] + hidden[i];
        g_res[i] = r;
        outres[i] = r;
    }
}

// ---------------- router top-k ----------------
__global__ void topk_kernel() {
    int t = blockIdx.x * 8 + (threadIdx.x >> 5);
    int lane = threadIdx.x & 31;
    const float* lg = g_logits + (size_t)t * E_;
    float v0 = lg[lane], v1 = lg[lane + 32];
    float mx = fmaxf(v0, v1);
#pragma unroll
    for (int o = 16; o; o >>= 1) mx = fmaxf(mx, __shfl_xor_sync(0xffffffffu, mx, o));
    float e0 = expf(v0 - mx), e1 = expf(v1 - mx);
    float ssum = e0 + e1;
#pragma unroll
    for (int o = 16; o; o >>= 1) ssum += __shfl_xor_sync(0xffffffffu, ssum, o);
    float p0 = e0 / ssum, p1 = e1 / ssum;
    float selv[TOPK_];
    int seli[TOPK_];
#pragma unroll
    for (int it = 0; it < TOPK_; it++) {
        float bv; int bi;
        if (p0 >= p1) { bv = p0; bi = lane; } else { bv = p1; bi = lane + 32; }
#pragma unroll
        for (int o = 16; o; o >>= 1) {
            float ov = __shfl_xor_sync(0xffffffffu, bv, o);
            int oi = __shfl_xor_sync(0xffffffffu, bi, o);
            if (ov > bv || (ov == bv && oi < bi)) { bv = ov; bi = oi; }
        }
        selv[it] = bv;
        seli[it] = bi;
        if (bi == lane) p0 = -1.f;
        if (bi == lane + 32) p1 = -1.f;
    }
    float tot = 0.f;
#pragma unroll
    for (int it = 0; it < TOPK_; it++) tot += selv[it];
    if (lane == 0) {
#pragma unroll
        for (int it = 0; it < TOPK_; it++) {
            g_topv[t * TOPK_ + it] = selv[it] / tot;
            g_topi[t * TOPK_ + it] = seli[it];
        }
    }
}

// ---------------- MoE routing bookkeeping ----------------
__global__ void zero_kernel() {
    int i = threadIdx.x;
    if (i < E_) { g_cnt[i] = 0; g_cur[i] = 0; }
}
__global__ void count_kernel() {
    int i = blockIdx.x * 256 + threadIdx.x;
    if (i < NTOK) atomicAdd(&g_cnt[g_topi[i]], 1);
}
__global__ void scan_kernel() {
    if (threadIdx.x == 0) {
        int a = 0;
        for (int e = 0; e < E_; e++) { g_off[e] = a; a += g_cnt[e]; }
        g_off[E_] = a;
    }
}
__global__ void assign_kernel() {
    int i = blockIdx.x * 256 + threadIdx.x;
    if (i < NTOK) {
        int e = g_topi[i];
        int r = g_off[e] + atomicAdd(&g_cur[e], 1);
        g_ptok[r] = i >> 3;
        g_rowof[i] = r;
    }
}

// ---------------- silu(gate) * up -> bf16 hi/lo ----------------
__global__ void silu_mul_kernel() {
    for (int i = blockIdx.x * 256 + threadIdx.x; i < NTOK * F_; i += gridDim.x * 256) {
        float g = g_gate[i];
        float u = g_up[i];
        float y = g / (1.f + __expf(-g)) * u;
        split2(y, g_a3h + i, g_a3l + i);
    }
}

// ---------------- combine expert outputs ----------------
__global__ void combine_kernel(float* __restrict__ out) {
    int t = blockIdx.x;
    float w[TOPK_];
    int rw[TOPK_];
#pragma unroll
    for (int j = 0; j < TOPK_; j++) {
        w[j] = g_topv[t * TOPK_ + j];
        rw[j] = g_rowof[t * TOPK_ + j];
    }
    for (int d = threadIdx.x; d < D_; d += 256) {
        float acc = 0.f;
#pragma unroll
        for (int j = 0; j < TOPK_; j++)
            acc += w[j] * g_ye[(size_t)rw[j] * D_ + d];
        out[(size_t)t * D_ + d] = acc;
    }
}

// ---------------- launch ----------------
extern "C" void kernel_launch(void* const* d_in, const int* in_sizes, int n_in,
                              void* d_out, int out_size) {
    const int* positions = (const int*)d_in[0];
    const float* hidden = (const float*)d_in[1];
    const float* in_ln = (const float*)d_in[2];
    const float* post_ln = (const float*)d_in[3];
    const float* qns = (const float*)d_in[4];
    const float* kns = (const float*)d_in[5];
    const float* wq = (const float*)d_in[6];
    const float* wk = (const float*)d_in[7];
    const float* wv = (const float*)d_in[8];
    const float* wo = (const float*)d_in[9];
    const float* wr = (const float*)d_in[10];
    const float* wg = (const float*)d_in[11];
    const float* wu = (const float*)d_in[12];
    const float* wd = (const float*)d_in[13];
    float* out = (float*)d_out;

    cudaFuncSetAttribute(mma_gemm, cudaFuncAttributeMaxDynamicSharedMemorySize, SM_TOTAL);
    cudaFuncSetAttribute(attn_kernel, cudaFuncAttributeMaxDynamicSharedMemorySize, AS_TOT);
    dim3 cb(32, 8);

    // weight convert + transpose (bf16 hi/lo, [N,K]); 64k x 32n tiles
    convsplit_kernel<<<dim3(4096 / 32, 2048 / 64, 1), cb>>>(wq, 0, 2048, 4096);
    convsplit_kernel<<<dim3(512 / 32, 2048 / 64, 1), cb>>>(wk, 1, 2048, 512);
    convsplit_kernel<<<dim3(512 / 32, 2048 / 64, 1), cb>>>(wv, 2, 2048, 512);
    convsplit_kernel<<<dim3(2048 / 32, 4096 / 64, 1), cb>>>(wo, 3, 4096, 2048);
    convsplit_kernel<<<dim3(768 / 32, 2048 / 64, 64), cb>>>(wg, 4, 2048, 768);
    convsplit_kernel<<<dim3(768 / 32, 2048 / 64, 64), cb>>>(wu, 5, 2048, 768);
    convsplit_kernel<<<dim3(2048 / 32, 768 / 64, 64), cb>>>(wd, 6, 768, 2048);
    rope_table_kernel<<<T_, 64>>>(positions);

    // pre-attention norm + QKV projections (HMMA bf16x3)
    rmsnorm_kernel<<<T_, 256>>>(hidden, 0, 0, in_ln);
    mma_gemm<<<dim3(32, 16, 1), 256, SM_TOTAL>>>(0, 0, 1, 0, 0, D_, HQ_ * HD_, 0);
    mma_gemm<<<dim3(4, 16, 1), 256, SM_TOTAL>>>(0, 1, 2, 0, 0, D_, HKV_ * HD_, 0);
    mma_gemm<<<dim3(4, 16, 1), 256, SM_TOTAL>>>(0, 2, 3, 0, 0, D_, HKV_ * HD_, 0);
    // per-head rmsnorm + rope
    qknorm_rope_kernel<<<dim3(T_, HQ_), HD_>>>(1, qns, HQ_);
    qknorm_rope_kernel<<<dim3(T_, HKV_), HD_>>>(2, kns, HKV_);
    // causal attention (HMMA) + output projection + residual
    attn_kernel<<<dim3(T_ / 64, HQ_), 128, AS_TOT>>>();
    mma_gemm<<<dim3(16, 16, 1), 256, SM_TOTAL>>>(1, 3, 5, 0, 0, HQ_ * HD_, D_, 0);
    resadd_kernel<<<2048, 256>>>(hidden, out + (size_t)T_ * D_);
    // post-attention norm + router (exact fp32) + top-k
    rmsnorm_kernel<<<T_, 256>>>(nullptr, 6, 2, post_ln);
    gemm_kernel<<<dim3(1, 16, 1), 256>>>(6, wr, 7, 0, 0, D_, E_, 0);
    topk_kernel<<<T_ / 8, 256>>>();
    // expert grouping
    zero_kernel<<<1, 64>>>();
    count_kernel<<<NTOK / 256, 256>>>();
    scan_kernel<<<1, 32>>>();
    assign_kernel<<<NTOK / 256, 256>>>();
    // expert GEMMs (HMMA, grouped, gathered)
    mma_gemm<<<dim3(6, 24, 64), 256, SM_TOTAL>>>(2, 4, 8, 1, 1, D_, F_, (long)F_ * D_);
    mma_gemm<<<dim3(6, 24, 64), 256, SM_TOTAL>>>(2, 5, 9, 1, 1, D_, F_, (long)F_ * D_);
    silu_mul_kernel<<<8192, 256>>>();
    mma_gemm<<<dim3(16, 24, 64), 256, SM_TOTAL>>>(3, 6, 10, 1, 0, F_, D_, (long)D_ * F_);
    combine_kernel<<<T_, 256>>>(out);
}